// round 7
// baseline (speedup 1.0000x reference)
#include <cuda_runtime.h>
#include <cstdint>
#include <math.h>

// ---------------- problem shapes (fixed) ----------------
#define Tc   4096
#define Dc   2048
#define Hc   16
#define Lc   12
#define LHc  192
#define Mc   8192          // B*T
#define KKc  2048          // GEMM K
#define EPSV 1.1920929e-07f
#define INVSQRT2 0.70710678118654752440f

typedef signed char i8;

// ---------------- scratch (static device globals; zero-initialized) ----------
__device__ i8    g_qxh[(size_t)Mc * Dc];
__device__ i8    g_qxl[(size_t)Mc * Dc];
__device__ i8    g_qwth[(size_t)Dc * Dc];
__device__ i8    g_qwtl[(size_t)Dc * Dc];
__device__ i8    g_qwoh[(size_t)Dc * Dc];
__device__ i8    g_qwol[(size_t)Dc * Dc];
__device__ i8    g_qwlh[(size_t)256 * Dc];   // W_lvl padded to 256 rows (pad stays 0)
__device__ i8    g_qwll[(size_t)256 * Dc];
__device__ i8    g_qth[(size_t)Mc * Dc];
__device__ i8    g_qtl[(size_t)Mc * Dc];
__device__ float g_sx [(size_t)Mc];
__device__ float g_swt[(size_t)Dc];
__device__ float g_swo[(size_t)Dc];
__device__ float g_swl[(size_t)256];
__device__ float g_sth[(size_t)Mc];
__device__ float g_theta [(size_t)Mc * Dc];
__device__ float g_phi   [(size_t)Mc * 256];   // padded cols
__device__ float g_tscale[(size_t)Mc];
__device__ float2 g_sc   [(size_t)2 * Hc * Lc * Tc];

// ---------------- PTX helpers ----------------
__device__ __forceinline__ uint32_t smem_u32(const void* p) {
    uint32_t a;
    asm("{ .reg .u64 t; cvta.to.shared.u64 t, %1; cvt.u32.u64 %0, t; }" : "=r"(a) : "l"(p));
    return a;
}
__device__ __forceinline__ void cp_async16(uint32_t s, const void* g) {
    asm volatile("cp.async.cg.shared.global [%0], [%1], 16;" :: "r"(s), "l"(g));
}
#define CP_COMMIT() asm volatile("cp.async.commit_group;" ::: "memory")
#define CP_WAIT1()  asm volatile("cp.async.wait_group 1;" ::: "memory")
#define CP_WAIT0()  asm volatile("cp.async.wait_group 0;" ::: "memory")

#define LDSM4(d0,d1,d2,d3,a) \
    asm volatile("ldmatrix.sync.aligned.m8n8.x4.shared.b16 {%0,%1,%2,%3}, [%4];" \
        : "=r"(d0), "=r"(d1), "=r"(d2), "=r"(d3) : "r"(a))

#define MMA_S8(c, a0,a1,a2,a3, b0,b1) \
    asm volatile("mma.sync.aligned.m16n8k32.row.col.s32.s8.s8.s32 " \
        "{%0,%1,%2,%3}, {%4,%5,%6,%7}, {%8,%9}, {%0,%1,%2,%3};" \
        : "+r"((c)[0]), "+r"((c)[1]), "+r"((c)[2]), "+r"((c)[3]) \
        : "r"(a0), "r"(a1), "r"(a2), "r"(a3), "r"(b0), "r"(b1))

// ---------------- int8 two-limb GEMM on legacy IMMA ----------------
// C[m,n] = sA[m]*sB[n] * sum_k qA[m,k]*qB[n,k], q = hi*128+lo (int8 limbs).
// acc_hi += Ah*Bh ; acc_x += Al*Bh + Ah*Bl ; lo*lo dropped (~1.5e-5).
// Block 128x128, 8 warps of 64x32, K chunk 64 int8, 2-stage cp.async.
#define RB    80                        // smem row bytes: 64 data + 16 pad
#define TILE  (128 * RB)                // 10240 B per limb tile
#define STG   (4 * TILE)                // Ahi,Alo,Bhi,Blo = 40960 B per stage
#define NCHI  (KKc / 64)                // 32 chunks

__global__ __launch_bounds__(256, 1)
void i8_gemm(const i8* __restrict__ Ah, const i8* __restrict__ Al,
             const float* __restrict__ sA,
             const i8* __restrict__ Bh, const i8* __restrict__ Bl,
             const float* __restrict__ sB,
             float* __restrict__ C, int NsMain, int nxMain,
             const i8* __restrict__ Bh2, const i8* __restrict__ Bl2,
             const float* __restrict__ sB2, float* __restrict__ C2)
{
    extern __shared__ char smem[];
    const uint32_t sb = smem_u32(smem);
    const int tid  = threadIdx.x;
    const int wid  = tid >> 5;
    const int lane = tid & 31;
    const int m0 = blockIdx.y * 128;
    const int wm = (wid & 1) * 64;
    const int wn = (wid >> 1) * 32;

    const i8* BhS; const i8* BlS; const float* sBS; float* CS; int n0, Ns;
    if ((int)blockIdx.x < nxMain) {
        BhS = Bh; BlS = Bl; sBS = sB; CS = C; n0 = blockIdx.x * 128; Ns = NsMain;
    } else {
        BhS = Bh2; BlS = Bl2; sBS = sB2; CS = C2; n0 = (blockIdx.x - nxMain) * 128; Ns = 256;
    }

    const int g = lane >> 3, r = lane & 7;
    uint32_t aOff[4], bOff[2];
    #pragma unroll
    for (int mt = 0; mt < 4; mt++)
        aOff[mt] = (uint32_t)((wm + mt * 16 + (g & 1) * 8 + r) * RB + (g >> 1) * 16);
    #pragma unroll
    for (int nt2 = 0; nt2 < 2; nt2++)
        bOff[nt2] = (uint32_t)((wn + nt2 * 16 + (g >> 1) * 8 + r) * RB + (g & 1) * 16);

    int accH[4][4][4], accX[4][4][4];
    #pragma unroll
    for (int i = 0; i < 4; i++)
        #pragma unroll
        for (int j = 0; j < 4; j++)
            #pragma unroll
            for (int v = 0; v < 4; v++) { accH[i][j][v] = 0; accX[i][j][v] = 0; }

    const i8* tp[4] = { Ah + (size_t)m0 * KKc, Al + (size_t)m0 * KKc,
                        BhS + (size_t)n0 * KKc, BlS + (size_t)n0 * KKc };

    auto load_stage = [&](int c, int st) {
        const uint32_t base = sb + st * STG;
        #pragma unroll
        for (int i = 0; i < 8; i++) {
            const int idx = tid + i * 256;           // 0..2047
            const int t   = idx >> 9;
            const int rem = idx & 511;
            const int row = rem >> 2;
            const int ch  = rem & 3;
            cp_async16(base + t * TILE + row * RB + ch * 16,
                       tp[t] + (size_t)row * KKc + c * 64 + ch * 16);
        }
        CP_COMMIT();
    };

    load_stage(0, 0);

    for (int c = 0; c < NCHI; c++) {
        if (c + 1 < NCHI) { load_stage(c + 1, (c + 1) & 1); CP_WAIT1(); }
        else              { CP_WAIT0(); }
        __syncthreads();

        const uint32_t stb = sb + (c & 1) * STG;
        #pragma unroll
        for (int ks = 0; ks < 2; ks++) {
            const uint32_t ko = ks * 32;
            uint32_t ahi[4][4], alo[4][4], bh[2][4], bl[2][4];

            #pragma unroll
            for (int mt = 0; mt < 4; mt++)
                LDSM4(ahi[mt][0], ahi[mt][1], ahi[mt][2], ahi[mt][3], stb + aOff[mt] + ko);
            #pragma unroll
            for (int nt2 = 0; nt2 < 2; nt2++)
                LDSM4(bh[nt2][0], bh[nt2][1], bh[nt2][2], bh[nt2][3], stb + 2 * TILE + bOff[nt2] + ko);

            // acc_hi += Ahi*Bhi
            #pragma unroll
            for (int mt = 0; mt < 4; mt++)
                #pragma unroll
                for (int nt = 0; nt < 4; nt++) {
                    const uint32_t* bb = &bh[nt >> 1][(nt & 1) * 2];
                    MMA_S8(accH[mt][nt], ahi[mt][0], ahi[mt][1], ahi[mt][2], ahi[mt][3], bb[0], bb[1]);
                }

            // acc_x += Alo*Bhi
            #pragma unroll
            for (int mt = 0; mt < 4; mt++)
                LDSM4(alo[mt][0], alo[mt][1], alo[mt][2], alo[mt][3], stb + TILE + aOff[mt] + ko);
            #pragma unroll
            for (int mt = 0; mt < 4; mt++)
                #pragma unroll
                for (int nt = 0; nt < 4; nt++) {
                    const uint32_t* bb = &bh[nt >> 1][(nt & 1) * 2];
                    MMA_S8(accX[mt][nt], alo[mt][0], alo[mt][1], alo[mt][2], alo[mt][3], bb[0], bb[1]);
                }

            // acc_x += Ahi*Blo
            #pragma unroll
            for (int nt2 = 0; nt2 < 2; nt2++)
                LDSM4(bl[nt2][0], bl[nt2][1], bl[nt2][2], bl[nt2][3], stb + 3 * TILE + bOff[nt2] + ko);
            #pragma unroll
            for (int mt = 0; mt < 4; mt++)
                #pragma unroll
                for (int nt = 0; nt < 4; nt++) {
                    const uint32_t* bb = &bl[nt >> 1][(nt & 1) * 2];
                    MMA_S8(accX[mt][nt], ahi[mt][0], ahi[mt][1], ahi[mt][2], ahi[mt][3], bb[0], bb[1]);
                }
        }
        __syncthreads();
    }

    // epilogue: C = sA*sB*(accH*2^14 + accX*2^7)
    #pragma unroll
    for (int mt = 0; mt < 4; mt++) {
        const int m = m0 + wm + mt * 16 + (lane >> 2);
        const float sa0 = sA[m], sa1 = sA[m + 8];
        #pragma unroll
        for (int nt = 0; nt < 4; nt++) {
            const int n = n0 + wn + nt * 8 + (lane & 3) * 2;
            const float sb0 = sBS[n], sb1 = sBS[n + 1];
            float v0 = (float)((long long)accH[mt][nt][0] * 16384ll + (long long)accX[mt][nt][0] * 128ll);
            float v1 = (float)((long long)accH[mt][nt][1] * 16384ll + (long long)accX[mt][nt][1] * 128ll);
            float v2 = (float)((long long)accH[mt][nt][2] * 16384ll + (long long)accX[mt][nt][2] * 128ll);
            float v3 = (float)((long long)accH[mt][nt][3] * 16384ll + (long long)accX[mt][nt][3] * 128ll);
            *(float2*)(CS + (size_t)m * Ns + n)       = make_float2(sa0 * sb0 * v0, sa0 * sb1 * v1);
            *(float2*)(CS + (size_t)(m + 8) * Ns + n) = make_float2(sa1 * sb0 * v2, sa1 * sb1 * v3);
        }
    }
}

// ---------------- per-row two-limb int8 quantization ----------------
// q = round(v * 16256/max), hi = (q+64)>>7, lo = q - hi*128.
__global__ __launch_bounds__(256)
void quant_rows(const float* __restrict__ X, i8* __restrict__ Qh, i8* __restrict__ Ql,
                float* __restrict__ scale)
{
    const int row = blockIdx.x;
    const int tid = threadIdx.x;
    const float* xr = X + (size_t)row * Dc;

    float v[8];
    float4 p0 = *(const float4*)(xr + tid * 8);
    float4 p1 = *(const float4*)(xr + tid * 8 + 4);
    v[0]=p0.x; v[1]=p0.y; v[2]=p0.z; v[3]=p0.w;
    v[4]=p1.x; v[5]=p1.y; v[6]=p1.z; v[7]=p1.w;

    float mx = 0.f;
    #pragma unroll
    for (int j = 0; j < 8; j++) mx = fmaxf(mx, fabsf(v[j]));
    #pragma unroll
    for (int o = 16; o > 0; o >>= 1) mx = fmaxf(mx, __shfl_xor_sync(0xffffffffu, mx, o));
    __shared__ float red[8];
    const int warp = tid >> 5, lane = tid & 31;
    if (lane == 0) red[warp] = mx;
    __syncthreads();
    mx = fmaxf(fmaxf(fmaxf(red[0], red[1]), fmaxf(red[2], red[3])),
               fmaxf(fmaxf(red[4], red[5]), fmaxf(red[6], red[7])));

    const float rs = (mx > 0.f) ? 16256.f / mx : 0.f;
    if (tid == 0) scale[row] = mx / 16256.f;

    uint32_t hw[2] = {0, 0}, lw[2] = {0, 0};
    #pragma unroll
    for (int j = 0; j < 8; j++) {
        int q  = __float2int_rn(v[j] * rs);
        int hi = (q + 64) >> 7;
        int lo = q - (hi << 7);
        hw[j >> 2] |= ((uint32_t)(uint8_t)(i8)hi) << ((j & 3) * 8);
        lw[j >> 2] |= ((uint32_t)(uint8_t)(i8)lo) << ((j & 3) * 8);
    }
    *(uint2*)(Qh + (size_t)row * Dc + tid * 8) = make_uint2(hw[0], hw[1]);
    *(uint2*)(Ql + (size_t)row * Dc + tid * 8) = make_uint2(lw[0], lw[1]);
}

// ---------------- theta RMS scale (per-row rsqrt only) ----------------
__global__ void rms_scale(const float* __restrict__ X, float* __restrict__ scale, int cols)
{
    const int row = blockIdx.x;
    const float* xr = X + (size_t)row * cols;
    float ss = 0.f;
    for (int c = threadIdx.x * 4; c < cols; c += blockDim.x * 4) {
        float4 v = *(const float4*)(xr + c);
        ss += v.x * v.x + v.y * v.y + v.z * v.z + v.w * v.w;
    }
    #pragma unroll
    for (int o = 16; o > 0; o >>= 1) ss += __shfl_xor_sync(0xffffffffu, ss, o);
    __shared__ float red[32];
    const int warp = threadIdx.x >> 5, lane = threadIdx.x & 31;
    if (lane == 0) red[warp] = ss;
    __syncthreads();
    if (warp == 0) {
        ss = (lane < (blockDim.x >> 5)) ? red[lane] : 0.f;
        #pragma unroll
        for (int o = 16; o > 0; o >>= 1) ss += __shfl_xor_sync(0xffffffffu, ss, o);
        if (lane == 0) scale[row] = rsqrtf(ss / (float)cols + EPSV);
    }
}

// ---------------- fused RMSNorm(phi) + sincos transpose ----------------
__global__ __launch_bounds__(192)
void phi_rms_sincos(const float* __restrict__ phi, float2* __restrict__ sc)
{
    const int row = blockIdx.x;            // b*4096 + t
    const int t   = row & (Tc - 1);
    const int b   = row >> 12;
    const int j   = threadIdx.x;           // 0..191
    const float v = phi[(size_t)row * 256 + j];

    float ss = v * v;
    #pragma unroll
    for (int o = 16; o > 0; o >>= 1) ss += __shfl_xor_sync(0xffffffffu, ss, o);
    __shared__ float red[6];
    const int warp = j >> 5, lane = j & 31;
    if (lane == 0) red[warp] = ss;
    __syncthreads();
    float tot = red[0] + red[1] + red[2] + red[3] + red[4] + red[5];
    const float rs = rsqrtf(tot / (float)LHc + EPSV);

    float s, c;
    sincosf(v * rs, &s, &c);
    const int l = j >> 4, h = j & 15;
    sc[((size_t)(b * Hc + h) * Lc + l) * Tc + t] = make_float2(c * INVSQRT2, s * INVSQRT2);
}

// ---------------- fused 12-level butterfly (in-place fp32) ----------------
__global__ __launch_bounds__(512, 1)
void butterfly_fused(float* __restrict__ theta, const float* __restrict__ tscale,
                     const float2* __restrict__ sc)
{
    extern __shared__ float th[];   // [4096][9]
    const int ds  = blockIdx.x;     // 0..15
    const int h   = blockIdx.y;     // 0..15
    const int b   = blockIdx.z;     // 0..1
    const int tid = threadIdx.x;
    const int cb  = h * 128 + ds * 8;
    const size_t rowbase = (size_t)b * Tc;

    #pragma unroll
    for (int k = 0; k < 8; k++) {
        const int t = tid + k * 512;
        const float scl = tscale[rowbase + t];
        const float* g = theta + (rowbase + t) * Dc + cb;
        float4 v0 = *(const float4*)g;
        float4 v1 = *(const float4*)(g + 4);
        float* s = &th[t * 9];
        s[0] = v0.x * scl; s[1] = v0.y * scl; s[2] = v0.z * scl; s[3] = v0.w * scl;
        s[4] = v1.x * scl; s[5] = v1.y * scl; s[6] = v1.z * scl; s[7] = v1.w * scl;
    }
    __syncthreads();

    const float2* scb = sc + (size_t)(b * Hc + h) * Lc * Tc;
    for (int l = 0; l < Lc; l++) {
        const int step = 1 << l;
        float2 w[8];
        #pragma unroll
        for (int k = 0; k < 8; k++) w[k] = scb[l * Tc + tid + k * 512];

        #pragma unroll
        for (int jh = 0; jh < 8; jh += 4) {
            float o[8][4];
            #pragma unroll
            for (int k = 0; k < 8; k++) {
                const int t = tid + k * 512;
                #pragma unroll
                for (int j = 0; j < 4; j++) {
                    float cur  = th[t * 9 + jh + j];
                    float prev = (t >= step) ? th[(t - step) * 9 + jh + j] : 0.f;
                    o[k][j] = fmaf(w[k].x, cur, w[k].y * prev);
                }
            }
            __syncthreads();
            #pragma unroll
            for (int k = 0; k < 8; k++) {
                const int t = tid + k * 512;
                #pragma unroll
                for (int j = 0; j < 4; j++) th[t * 9 + jh + j] = o[k][j];
            }
            __syncthreads();
        }
    }

    #pragma unroll
    for (int k = 0; k < 8; k++) {
        const int t = tid + k * 512;
        const float* s = &th[t * 9];
        float* g = theta + (rowbase + t) * Dc + cb;
        *(float4*)g       = make_float4(s[0], s[1], s[2], s[3]);
        *(float4*)(g + 4) = make_float4(s[4], s[5], s[6], s[7]);
    }
}

// ---------------- launcher ----------------
extern "C" void kernel_launch(void* const* d_in, const int* in_sizes, int n_in,
                              void* d_out, int out_size)
{
    const float* x     = (const float*)d_in[0];
    const float* W_tok = (const float*)d_in[1];
    const float* W_lvl = (const float*)d_in[2];
    const float* W_out = (const float*)d_in[3];
    float* out = (float*)d_out;

    i8 *qxh, *qxl, *qwth, *qwtl, *qwoh, *qwol, *qwlh, *qwll, *qth, *qtl;
    float *sx, *swt, *swo, *swl, *sth, *theta, *phi, *tscale; float2* sc;
    cudaGetSymbolAddress((void**)&qxh, g_qxh);   cudaGetSymbolAddress((void**)&qxl, g_qxl);
    cudaGetSymbolAddress((void**)&qwth, g_qwth); cudaGetSymbolAddress((void**)&qwtl, g_qwtl);
    cudaGetSymbolAddress((void**)&qwoh, g_qwoh); cudaGetSymbolAddress((void**)&qwol, g_qwol);
    cudaGetSymbolAddress((void**)&qwlh, g_qwlh); cudaGetSymbolAddress((void**)&qwll, g_qwll);
    cudaGetSymbolAddress((void**)&qth, g_qth);   cudaGetSymbolAddress((void**)&qtl, g_qtl);
    cudaGetSymbolAddress((void**)&sx,  g_sx);    cudaGetSymbolAddress((void**)&swt, g_swt);
    cudaGetSymbolAddress((void**)&swo, g_swo);   cudaGetSymbolAddress((void**)&swl, g_swl);
    cudaGetSymbolAddress((void**)&sth, g_sth);
    cudaGetSymbolAddress((void**)&theta,  g_theta);
    cudaGetSymbolAddress((void**)&phi,    g_phi);
    cudaGetSymbolAddress((void**)&tscale, g_tscale);
    cudaGetSymbolAddress((void**)&sc,     g_sc);

    const int SMEM_GEMM = 2 * STG;              // 81920
    const int SMEM_BFLY = 4096 * 9 * 4;         // 147456
    cudaFuncSetAttribute(i8_gemm, cudaFuncAttributeMaxDynamicSharedMemorySize, SMEM_GEMM);
    cudaFuncSetAttribute(butterfly_fused, cudaFuncAttributeMaxDynamicSharedMemorySize, SMEM_BFLY);

    // 1) quantize inputs (per-row two-limb int8)
    quant_rows<<<Mc,   256>>>(x,     qxh,  qxl,  sx);
    quant_rows<<<Dc,   256>>>(W_tok, qwth, qwtl, swt);
    quant_rows<<<Dc,   256>>>(W_out, qwoh, qwol, swo);
    quant_rows<<<LHc,  256>>>(W_lvl, qwlh, qwll, swl);

    // 2) merged GEMM: theta = x@W_tok^T (bx 0..15), phi = x@W_lvl^T (bx 16..17)
    i8_gemm<<<dim3(18, Mc / 128), 256, SMEM_GEMM>>>(qxh, qxl, sx, qwth, qwtl, swt,
                                                    theta, Dc, 16,
                                                    qwlh, qwll, swl, phi);

    // 3) norms
    rms_scale<<<Mc, 256>>>(theta, tscale, Dc);
    phi_rms_sincos<<<Mc, 192>>>(phi, sc);

    // 4) fused butterfly (12 levels, applies tscale, in place)
    butterfly_fused<<<dim3(16, Hc, 2), 512, SMEM_BFLY>>>(theta, tscale, sc);

    // 5) quantize theta, final GEMM: y = theta @ W_out^T
    quant_rows<<<Mc, 256>>>(theta, qth, qtl, sth);
    i8_gemm<<<dim3(16, Mc / 128), 256, SMEM_GEMM>>>(qth, qtl, sth, qwoh, qwol, swo,
                                                    out, Dc, 16,
                                                    nullptr, nullptr, nullptr, nullptr);
}

// round 8
// speedup vs baseline: 2.9313x; 2.9313x over previous
#include <cuda_runtime.h>
#include <cuda_bf16.h>
#include <cuda_fp16.h>
#include <cstdint>
#include <math.h>

// ---------------- problem shapes (fixed) ----------------
#define Tc   4096
#define Dc   2048
#define Hc   16
#define Lc   12
#define LHc  192
#define Mc   8192          // B*T
#define KKc  2048          // GEMM K
#define EPSV 1.1920929e-07f
#define INVSQRT2 0.70710678118654752440f

typedef __nv_bfloat16 bf16;

// ---------------- scratch (static device globals; zero-initialized) ----------
__device__ bf16  g_xh [(size_t)Mc * Dc];
__device__ bf16  g_xl [(size_t)Mc * Dc];
__device__ bf16  g_wth[(size_t)Dc * Dc];
__device__ bf16  g_wtl[(size_t)Dc * Dc];
__device__ __half g_woh[(size_t)Dc * Dc];   // W_out single fp16
__device__ bf16  g_wlh[(size_t)256 * Dc];   // W_lvl padded 192->256 rows (pad stays 0)
__device__ bf16  g_wll[(size_t)256 * Dc];
__device__ __half g_thh[(size_t)Mc * Dc];   // theta fp16 hi
__device__ __half g_thl[(size_t)Mc * Dc];   // theta fp16 lo
__device__ float g_theta [(size_t)Mc * Dc];
__device__ float g_phi   [(size_t)Mc * 256];   // padded cols
__device__ float g_tscale[(size_t)Mc];
__device__ float2 g_sc   [(size_t)2 * Hc * Lc * Tc];

// ---------------- PTX helpers ----------------
__device__ __forceinline__ uint32_t smem_u32(const void* p) {
    uint32_t a;
    asm("{ .reg .u64 t; cvta.to.shared.u64 t, %1; cvt.u32.u64 %0, t; }" : "=r"(a) : "l"(p));
    return a;
}
__device__ __forceinline__ void cp_async16(uint32_t s, const void* g) {
    asm volatile("cp.async.cg.shared.global [%0], [%1], 16;" :: "r"(s), "l"(g));
}
#define CP_COMMIT() asm volatile("cp.async.commit_group;" ::: "memory")
#define CP_WAIT1()  asm volatile("cp.async.wait_group 1;" ::: "memory")
#define CP_WAIT0()  asm volatile("cp.async.wait_group 0;" ::: "memory")

#define LDSM4(d0,d1,d2,d3,a) \
    asm volatile("ldmatrix.sync.aligned.m8n8.x4.shared.b16 {%0,%1,%2,%3}, [%4];" \
        : "=r"(d0), "=r"(d1), "=r"(d2), "=r"(d3) : "r"(a))

#define MMA_BF16(c, a0,a1,a2,a3, b0,b1) \
    asm volatile("mma.sync.aligned.m16n8k16.row.col.f32.bf16.bf16.f32 " \
        "{%0,%1,%2,%3}, {%4,%5,%6,%7}, {%8,%9}, {%0,%1,%2,%3};" \
        : "+f"((c)[0]), "+f"((c)[1]), "+f"((c)[2]), "+f"((c)[3]) \
        : "r"(a0), "r"(a1), "r"(a2), "r"(a3), "r"(b0), "r"(b1))

#define MMA_F16(c, a0,a1,a2,a3, b0,b1) \
    asm volatile("mma.sync.aligned.m16n8k16.row.col.f32.f16.f16.f32 " \
        "{%0,%1,%2,%3}, {%4,%5,%6,%7}, {%8,%9}, {%0,%1,%2,%3};" \
        : "+f"((c)[0]), "+f"((c)[1]), "+f"((c)[2]), "+f"((c)[3]) \
        : "r"(a0), "r"(a1), "r"(a2), "r"(a3), "r"(b0), "r"(b1))

// ================= GEMM A: bf16 3-term split (theta & phi) ==================
// C[m,n] = sum_k A[m,k]*B[n,k]; A~Ah+Al, B~Bh+Bl (bf16), fp32 accum.
// Block 128x128, 4 warps of 64x64, K chunk 32, 2-stage cp.async, 2 CTAs/SM.
#define RB    80                        // smem row bytes: 32 bf16 (64B) + 16B pad
#define TILE  (128 * RB)                // 10240 B per operand tile
#define STG   (4 * TILE)                // Ah,Al,Bh,Bl per stage = 40960 B
#define NCH   (KKc / 32)                // 64 chunks

__global__ __launch_bounds__(128, 2)
void mma_gemm(const bf16* __restrict__ Ah, const bf16* __restrict__ Al,
              const bf16* __restrict__ Bh, const bf16* __restrict__ Bl,
              float* __restrict__ C, int NsMain, int nxMain,
              const bf16* __restrict__ Bh2, const bf16* __restrict__ Bl2,
              float* __restrict__ C2)
{
    extern __shared__ char smem[];
    const uint32_t sb = smem_u32(smem);
    const int tid  = threadIdx.x;
    const int wid  = tid >> 5;
    const int lane = tid & 31;
    const int m0 = blockIdx.y * 128;
    const int wm = (wid & 1) * 64;
    const int wn = (wid >> 1) * 64;

    const bf16* BhS; const bf16* BlS; float* CS; int n0, Ns;
    if ((int)blockIdx.x < nxMain) {
        BhS = Bh; BlS = Bl; CS = C; n0 = blockIdx.x * 128; Ns = NsMain;
    } else {
        BhS = Bh2; BlS = Bl2; CS = C2; n0 = (blockIdx.x - nxMain) * 128; Ns = 256;
    }

    const int g = lane >> 3, r = lane & 7;
    uint32_t aOff[4], bOff[4];
    #pragma unroll
    for (int mt = 0; mt < 4; mt++)
        aOff[mt] = (uint32_t)((wm + mt * 16 + (g & 1) * 8 + r) * RB + (g >> 1) * 16);
    #pragma unroll
    for (int nt2 = 0; nt2 < 4; nt2++)
        bOff[nt2] = (uint32_t)(2 * TILE + (wn + nt2 * 16 + (g >> 1) * 8 + r) * RB + (g & 1) * 16);

    float acc[4][8][4];
    #pragma unroll
    for (int i = 0; i < 4; i++)
        #pragma unroll
        for (int j = 0; j < 8; j++)
            #pragma unroll
            for (int v = 0; v < 4; v++) acc[i][j][v] = 0.f;

    const bf16* tp[4] = { Ah + (size_t)m0 * KKc, Al + (size_t)m0 * KKc,
                          BhS + (size_t)n0 * KKc, BlS + (size_t)n0 * KKc };

    auto load_stage = [&](int c, int st) {
        const uint32_t base = sb + st * STG;
        #pragma unroll
        for (int t = 0; t < 4; t++) {
            const bf16* src = tp[t] + c * 32;
            #pragma unroll
            for (int i = 0; i < 4; i++) {
                const int idx = tid + i * 128;       // 0..511
                const int row = idx >> 2;
                const int ch  = idx & 3;
                cp_async16(base + t * TILE + row * RB + ch * 16,
                           src + (size_t)row * KKc + ch * 8);
            }
        }
        CP_COMMIT();
    };

    load_stage(0, 0);

    for (int c = 0; c < NCH; c++) {
        if (c + 1 < NCH) { load_stage(c + 1, (c + 1) & 1); CP_WAIT1(); }
        else             { CP_WAIT0(); }
        __syncthreads();

        const uint32_t stb = sb + (c & 1) * STG;
        #pragma unroll
        for (int ks = 0; ks < 2; ks++) {
            const uint32_t ko = ks * 32;
            uint32_t ah[4][4], bh[4][4], xx[4][4];

            #pragma unroll
            for (int mt = 0; mt < 4; mt++)
                LDSM4(ah[mt][0], ah[mt][1], ah[mt][2], ah[mt][3], stb + aOff[mt] + ko);
            #pragma unroll
            for (int nt2 = 0; nt2 < 4; nt2++)
                LDSM4(bh[nt2][0], bh[nt2][1], bh[nt2][2], bh[nt2][3], stb + bOff[nt2] + ko);
            #pragma unroll
            for (int mt = 0; mt < 4; mt++)
                #pragma unroll
                for (int nt = 0; nt < 8; nt++) {
                    const uint32_t* bb = &bh[nt >> 1][(nt & 1) * 2];
                    MMA_BF16(acc[mt][nt], ah[mt][0], ah[mt][1], ah[mt][2], ah[mt][3], bb[0], bb[1]);
                }

            #pragma unroll
            for (int mt = 0; mt < 4; mt++)
                LDSM4(xx[mt][0], xx[mt][1], xx[mt][2], xx[mt][3], stb + TILE + aOff[mt] + ko);
            #pragma unroll
            for (int mt = 0; mt < 4; mt++)
                #pragma unroll
                for (int nt = 0; nt < 8; nt++) {
                    const uint32_t* bb = &bh[nt >> 1][(nt & 1) * 2];
                    MMA_BF16(acc[mt][nt], xx[mt][0], xx[mt][1], xx[mt][2], xx[mt][3], bb[0], bb[1]);
                }

            #pragma unroll
            for (int nt2 = 0; nt2 < 4; nt2++)
                LDSM4(xx[nt2][0], xx[nt2][1], xx[nt2][2], xx[nt2][3], stb + TILE + bOff[nt2] + ko);
            #pragma unroll
            for (int mt = 0; mt < 4; mt++)
                #pragma unroll
                for (int nt = 0; nt < 8; nt++) {
                    const uint32_t* bb = &xx[nt >> 1][(nt & 1) * 2];
                    MMA_BF16(acc[mt][nt], ah[mt][0], ah[mt][1], ah[mt][2], ah[mt][3], bb[0], bb[1]);
                }
        }
        __syncthreads();
    }

    #pragma unroll
    for (int mt = 0; mt < 4; mt++) {
        const int m = m0 + wm + mt * 16 + (lane >> 2);
        #pragma unroll
        for (int nt = 0; nt < 8; nt++) {
            const int n = n0 + wn + nt * 8 + (lane & 3) * 2;
            *(float2*)(CS + (size_t)m * Ns + n)       = make_float2(acc[mt][nt][0], acc[mt][nt][1]);
            *(float2*)(CS + (size_t)(m + 8) * Ns + n) = make_float2(acc[mt][nt][2], acc[mt][nt][3]);
        }
    }
}

// ================= GEMM B: fp16 2-term (final projection) ===================
// C = (Ah+Al) @ Bh^T; Ah,Al fp16 split of theta (exact to 2^-22), Bh fp16 W_out.
// Block 128x128, 4 warps of 64x64, K chunk 32, 3-stage, 1 sync/chunk.
#define STG3  (3 * TILE)                // Ah,Al,Bh per stage = 30720 B

__global__ __launch_bounds__(128, 2)
void f16_gemm(const __half* __restrict__ Ah, const __half* __restrict__ Al,
              const __half* __restrict__ Bh, float* __restrict__ C)
{
    extern __shared__ char smem[];
    const uint32_t sb = smem_u32(smem);
    const int tid  = threadIdx.x;
    const int wid  = tid >> 5;
    const int lane = tid & 31;
    const int m0 = blockIdx.y * 128;
    const int n0 = blockIdx.x * 128;
    const int wm = (wid & 1) * 64;
    const int wn = (wid >> 1) * 64;

    const int g = lane >> 3, r = lane & 7;
    uint32_t aOff[4], bOff[4];
    #pragma unroll
    for (int mt = 0; mt < 4; mt++)
        aOff[mt] = (uint32_t)((wm + mt * 16 + (g & 1) * 8 + r) * RB + (g >> 1) * 16);
    #pragma unroll
    for (int nt2 = 0; nt2 < 4; nt2++)
        bOff[nt2] = (uint32_t)(2 * TILE + (wn + nt2 * 16 + (g >> 1) * 8 + r) * RB + (g & 1) * 16);

    float acc[4][8][4];
    #pragma unroll
    for (int i = 0; i < 4; i++)
        #pragma unroll
        for (int j = 0; j < 8; j++)
            #pragma unroll
            for (int v = 0; v < 4; v++) acc[i][j][v] = 0.f;

    const __half* tp[3] = { Ah + (size_t)m0 * KKc, Al + (size_t)m0 * KKc,
                            Bh + (size_t)n0 * KKc };

    auto load_stage = [&](int c, int st) {
        const uint32_t base = sb + st * STG3;
        #pragma unroll
        for (int t = 0; t < 3; t++) {
            const __half* src = tp[t] + c * 32;
            #pragma unroll
            for (int i = 0; i < 4; i++) {
                const int idx = tid + i * 128;       // 0..511
                const int row = idx >> 2;
                const int ch  = idx & 3;
                cp_async16(base + t * TILE + row * RB + ch * 16,
                           src + (size_t)row * KKc + ch * 8);
            }
        }
        CP_COMMIT();
    };

    load_stage(0, 0);
    load_stage(1, 1);

    for (int c = 0; c < NCH; c++) {
        if (c + 1 < NCH) CP_WAIT1(); else CP_WAIT0();
        __syncthreads();
        if (c + 2 < NCH) load_stage(c + 2, (c + 2) % 3);

        const uint32_t stb = sb + (c % 3) * STG3;
        #pragma unroll
        for (int ks = 0; ks < 2; ks++) {
            const uint32_t ko = ks * 32;
            uint32_t ah[4][4], bh[4][4], al[4][4];

            #pragma unroll
            for (int mt = 0; mt < 4; mt++)
                LDSM4(ah[mt][0], ah[mt][1], ah[mt][2], ah[mt][3], stb + aOff[mt] + ko);
            #pragma unroll
            for (int nt2 = 0; nt2 < 4; nt2++)
                LDSM4(bh[nt2][0], bh[nt2][1], bh[nt2][2], bh[nt2][3], stb + bOff[nt2] + ko);
            #pragma unroll
            for (int mt = 0; mt < 4; mt++)
                #pragma unroll
                for (int nt = 0; nt < 8; nt++) {
                    const uint32_t* bb = &bh[nt >> 1][(nt & 1) * 2];
                    MMA_F16(acc[mt][nt], ah[mt][0], ah[mt][1], ah[mt][2], ah[mt][3], bb[0], bb[1]);
                }

            #pragma unroll
            for (int mt = 0; mt < 4; mt++)
                LDSM4(al[mt][0], al[mt][1], al[mt][2], al[mt][3], stb + TILE + aOff[mt] + ko);
            #pragma unroll
            for (int mt = 0; mt < 4; mt++)
                #pragma unroll
                for (int nt = 0; nt < 8; nt++) {
                    const uint32_t* bb = &bh[nt >> 1][(nt & 1) * 2];
                    MMA_F16(acc[mt][nt], al[mt][0], al[mt][1], al[mt][2], al[mt][3], bb[0], bb[1]);
                }
        }
    }

    #pragma unroll
    for (int mt = 0; mt < 4; mt++) {
        const int m = m0 + wm + mt * 16 + (lane >> 2);
        #pragma unroll
        for (int nt = 0; nt < 8; nt++) {
            const int n = n0 + wn + nt * 8 + (lane & 3) * 2;
            *(float2*)(C + (size_t)m * Dc + n)       = make_float2(acc[mt][nt][0], acc[mt][nt][1]);
            *(float2*)(C + (size_t)(m + 8) * Dc + n) = make_float2(acc[mt][nt][2], acc[mt][nt][3]);
        }
    }
}

// ---------------- fp32 -> bf16 hi/lo split ----------------
__global__ void split_bf16(const float4* __restrict__ src,
                           uint2* __restrict__ H, uint2* __restrict__ L, int n4)
{
    int i = blockIdx.x * blockDim.x + threadIdx.x;
    if (i >= n4) return;
    float4 v = src[i];
    bf16 h0 = __float2bfloat16(v.x), h1 = __float2bfloat16(v.y);
    bf16 h2 = __float2bfloat16(v.z), h3 = __float2bfloat16(v.w);
    bf16 l0 = __float2bfloat16(v.x - __bfloat162float(h0));
    bf16 l1 = __float2bfloat16(v.y - __bfloat162float(h1));
    bf16 l2 = __float2bfloat16(v.z - __bfloat162float(h2));
    bf16 l3 = __float2bfloat16(v.w - __bfloat162float(h3));
    __nv_bfloat162 ha = {h0, h1}, hb = {h2, h3}, la = {l0, l1}, lb = {l2, l3};
    H[i] = make_uint2(*(uint32_t*)&ha, *(uint32_t*)&hb);
    L[i] = make_uint2(*(uint32_t*)&la, *(uint32_t*)&lb);
}

// ---------------- fp32 -> fp16 (single, rn) ----------------
__global__ void cvt_f16(const float4* __restrict__ src, uint2* __restrict__ H, int n4)
{
    int i = blockIdx.x * blockDim.x + threadIdx.x;
    if (i >= n4) return;
    float4 v = src[i];
    __half2 a = __floats2half2_rn(v.x, v.y);
    __half2 b = __floats2half2_rn(v.z, v.w);
    H[i] = make_uint2(*(uint32_t*)&a, *(uint32_t*)&b);
}

// ---------------- theta RMS scale (per-row rsqrt only) ----------------
__global__ void rms_scale(const float* __restrict__ X, float* __restrict__ scale, int cols)
{
    const int row = blockIdx.x;
    const float* xr = X + (size_t)row * cols;
    float ss = 0.f;
    for (int c = threadIdx.x * 4; c < cols; c += blockDim.x * 4) {
        float4 v = *(const float4*)(xr + c);
        ss += v.x * v.x + v.y * v.y + v.z * v.z + v.w * v.w;
    }
    #pragma unroll
    for (int o = 16; o > 0; o >>= 1) ss += __shfl_xor_sync(0xffffffffu, ss, o);
    __shared__ float red[32];
    const int warp = threadIdx.x >> 5, lane = threadIdx.x & 31;
    if (lane == 0) red[warp] = ss;
    __syncthreads();
    if (warp == 0) {
        ss = (lane < (blockDim.x >> 5)) ? red[lane] : 0.f;
        #pragma unroll
        for (int o = 16; o > 0; o >>= 1) ss += __shfl_xor_sync(0xffffffffu, ss, o);
        if (lane == 0) scale[row] = rsqrtf(ss / (float)cols + EPSV);
    }
}

// ---------------- fused RMSNorm(phi) + sincos transpose ----------------
__global__ __launch_bounds__(192)
void phi_rms_sincos(const float* __restrict__ phi, float2* __restrict__ sc)
{
    const int row = blockIdx.x;            // b*4096 + t
    const int t   = row & (Tc - 1);
    const int b   = row >> 12;
    const int j   = threadIdx.x;           // 0..191
    const float v = phi[(size_t)row * 256 + j];

    float ss = v * v;
    #pragma unroll
    for (int o = 16; o > 0; o >>= 1) ss += __shfl_xor_sync(0xffffffffu, ss, o);
    __shared__ float red[6];
    const int warp = j >> 5, lane = j & 31;
    if (lane == 0) red[warp] = ss;
    __syncthreads();
    float tot = red[0] + red[1] + red[2] + red[3] + red[4] + red[5];
    const float rs = rsqrtf(tot / (float)LHc + EPSV);

    float s, c;
    sincosf(v * rs, &s, &c);
    const int l = j >> 4, h = j & 15;
    sc[((size_t)(b * Hc + h) * Lc + l) * Tc + t] = make_float2(c * INVSQRT2, s * INVSQRT2);
}

// ---------------- fused 12-level butterfly -> fp16 hi/lo ----------------
__global__ __launch_bounds__(512, 1)
void butterfly_fused(const float* __restrict__ theta, const float* __restrict__ tscale,
                     const float2* __restrict__ sc,
                     __half* __restrict__ Th, __half* __restrict__ Tl)
{
    extern __shared__ float th[];   // [4096][9]
    const int ds  = blockIdx.x;     // 0..15
    const int h   = blockIdx.y;     // 0..15
    const int b   = blockIdx.z;     // 0..1
    const int tid = threadIdx.x;
    const int cb  = h * 128 + ds * 8;
    const size_t rowbase = (size_t)b * Tc;

    #pragma unroll
    for (int k = 0; k < 8; k++) {
        const int t = tid + k * 512;
        const float scl = tscale[rowbase + t];
        const float* g = theta + (rowbase + t) * Dc + cb;
        float4 v0 = *(const float4*)g;
        float4 v1 = *(const float4*)(g + 4);
        float* s = &th[t * 9];
        s[0] = v0.x * scl; s[1] = v0.y * scl; s[2] = v0.z * scl; s[3] = v0.w * scl;
        s[4] = v1.x * scl; s[5] = v1.y * scl; s[6] = v1.z * scl; s[7] = v1.w * scl;
    }
    __syncthreads();

    const float2* scb = sc + (size_t)(b * Hc + h) * Lc * Tc;
    for (int l = 0; l < Lc; l++) {
        const int step = 1 << l;
        float2 w[8];
        #pragma unroll
        for (int k = 0; k < 8; k++) w[k] = scb[l * Tc + tid + k * 512];

        #pragma unroll
        for (int jh = 0; jh < 8; jh += 4) {
            float o[8][4];
            #pragma unroll
            for (int k = 0; k < 8; k++) {
                const int t = tid + k * 512;
                #pragma unroll
                for (int j = 0; j < 4; j++) {
                    float cur  = th[t * 9 + jh + j];
                    float prev = (t >= step) ? th[(t - step) * 9 + jh + j] : 0.f;
                    o[k][j] = fmaf(w[k].x, cur, w[k].y * prev);
                }
            }
            __syncthreads();
            #pragma unroll
            for (int k = 0; k < 8; k++) {
                const int t = tid + k * 512;
                #pragma unroll
                for (int j = 0; j < 4; j++) th[t * 9 + jh + j] = o[k][j];
            }
            __syncthreads();
        }
    }

    #pragma unroll
    for (int k = 0; k < 8; k++) {
        const int t = tid + k * 512;
        const float* s = &th[t * 9];
        __half hh[8], ll[8];
        #pragma unroll
        for (int j = 0; j < 8; j++) {
            float v = s[j];
            hh[j] = __float2half_rn(v);
            ll[j] = __float2half_rn(v - __half2float(hh[j]));
        }
        *(uint4*)(Th + (rowbase + t) * Dc + cb) = *(uint4*)hh;
        *(uint4*)(Tl + (rowbase + t) * Dc + cb) = *(uint4*)ll;
    }
}

// ---------------- launcher ----------------
extern "C" void kernel_launch(void* const* d_in, const int* in_sizes, int n_in,
                              void* d_out, int out_size)
{
    const float* x     = (const float*)d_in[0];
    const float* W_tok = (const float*)d_in[1];
    const float* W_lvl = (const float*)d_in[2];
    const float* W_out = (const float*)d_in[3];
    float* out = (float*)d_out;

    bf16 *xh, *xl, *wth, *wtl, *wlh, *wll;
    __half *woh, *thh, *thl;
    float *theta, *phi, *tscale; float2* sc;
    cudaGetSymbolAddress((void**)&xh,  g_xh);   cudaGetSymbolAddress((void**)&xl,  g_xl);
    cudaGetSymbolAddress((void**)&wth, g_wth);  cudaGetSymbolAddress((void**)&wtl, g_wtl);
    cudaGetSymbolAddress((void**)&woh, g_woh);
    cudaGetSymbolAddress((void**)&wlh, g_wlh);  cudaGetSymbolAddress((void**)&wll, g_wll);
    cudaGetSymbolAddress((void**)&thh, g_thh);  cudaGetSymbolAddress((void**)&thl, g_thl);
    cudaGetSymbolAddress((void**)&theta,  g_theta);
    cudaGetSymbolAddress((void**)&phi,    g_phi);
    cudaGetSymbolAddress((void**)&tscale, g_tscale);
    cudaGetSymbolAddress((void**)&sc,     g_sc);

    const int SMEM_GEMM  = 2 * STG;             // 81920
    const int SMEM_GEMM3 = 3 * STG3;            // 92160
    const int SMEM_BFLY  = 4096 * 9 * 4;        // 147456
    cudaFuncSetAttribute(mma_gemm, cudaFuncAttributeMaxDynamicSharedMemorySize, SMEM_GEMM);
    cudaFuncSetAttribute(f16_gemm, cudaFuncAttributeMaxDynamicSharedMemorySize, SMEM_GEMM3);
    cudaFuncSetAttribute(butterfly_fused, cudaFuncAttributeMaxDynamicSharedMemorySize, SMEM_BFLY);

    // 1) operand conversions
    split_bf16<<<(Mc * Dc / 4 + 255) / 256, 256>>>((const float4*)x, (uint2*)xh, (uint2*)xl, Mc * Dc / 4);
    split_bf16<<<(Dc * Dc / 4 + 255) / 256, 256>>>((const float4*)W_tok, (uint2*)wth, (uint2*)wtl, Dc * Dc / 4);
    split_bf16<<<(LHc * Dc / 4 + 255) / 256, 256>>>((const float4*)W_lvl, (uint2*)wlh, (uint2*)wll, LHc * Dc / 4);
    cvt_f16<<<(Dc * Dc / 4 + 255) / 256, 256>>>((const float4*)W_out, (uint2*)woh, Dc * Dc / 4);

    // 2) merged GEMM: theta = x@W_tok^T (bx 0..15), phi = x@W_lvl^T (bx 16..17)
    mma_gemm<<<dim3(18, Mc / 128), 128, SMEM_GEMM>>>(xh, xl, wth, wtl, theta, Dc, 16,
                                                     wlh, wll, phi);

    // 3) norms
    rms_scale<<<Mc, 256>>>(theta, tscale, Dc);
    phi_rms_sincos<<<Mc, 192>>>(phi, sc);

    // 4) fused butterfly (12 levels, applies tscale), emits fp16 hi/lo
    butterfly_fused<<<dim3(16, Hc, 2), 512, SMEM_BFLY>>>(theta, tscale, sc, thh, thl);

    // 5) y = theta @ W_out^T  (fp16 2-term)
    f16_gemm<<<dim3(16, Mc / 128), 128, SMEM_GEMM3>>>(thh, thl, woh, out);
}

// round 9
// speedup vs baseline: 3.5583x; 1.2139x over previous
#include <cuda_runtime.h>
#include <cuda_fp16.h>
#include <cstdint>
#include <math.h>

// ---------------- problem shapes (fixed) ----------------
#define Tc   4096
#define Dc   2048
#define Hc   16
#define Lc   12
#define LHc  192
#define Mc   8192          // B*T
#define KKc  2048          // GEMM K
#define EPSV 1.1920929e-07f
#define INVSQRT2 0.70710678118654752440f

// ---------------- scratch (static device globals; zero-initialized) ----------
__device__ __half g_xh [(size_t)Mc * Dc];      // x fp16 hi
__device__ __half g_xl [(size_t)Mc * Dc];      // x fp16 lo
__device__ __half g_wth[(size_t)Dc * Dc];      // W_tok fp16
__device__ __half g_woh[(size_t)Dc * Dc];      // W_out fp16
__device__ __half g_wlh[(size_t)256 * Dc];     // W_lvl fp16, padded 192->256 rows (pad 0)
__device__ __half g_thh[(size_t)Mc * Dc];      // theta fp16 hi
__device__ __half g_thl[(size_t)Mc * Dc];      // theta fp16 lo
__device__ float g_theta [(size_t)Mc * Dc];
__device__ float g_phi   [(size_t)Mc * 256];   // padded cols
__device__ float g_tscale[(size_t)Mc];
__device__ float2 g_sc   [(size_t)2 * Hc * Lc * Tc];

// ---------------- PTX helpers ----------------
__device__ __forceinline__ uint32_t smem_u32(const void* p) {
    uint32_t a;
    asm("{ .reg .u64 t; cvta.to.shared.u64 t, %1; cvt.u32.u64 %0, t; }" : "=r"(a) : "l"(p));
    return a;
}
__device__ __forceinline__ void cp_async16(uint32_t s, const void* g) {
    asm volatile("cp.async.cg.shared.global [%0], [%1], 16;" :: "r"(s), "l"(g));
}
#define CP_COMMIT() asm volatile("cp.async.commit_group;" ::: "memory")
#define CP_WAIT1()  asm volatile("cp.async.wait_group 1;" ::: "memory")
#define CP_WAIT0()  asm volatile("cp.async.wait_group 0;" ::: "memory")

#define LDSM4(d0,d1,d2,d3,a) \
    asm volatile("ldmatrix.sync.aligned.m8n8.x4.shared.b16 {%0,%1,%2,%3}, [%4];" \
        : "=r"(d0), "=r"(d1), "=r"(d2), "=r"(d3) : "r"(a))

#define MMA_F16(c, a0,a1,a2,a3, b0,b1) \
    asm volatile("mma.sync.aligned.m16n8k16.row.col.f32.f16.f16.f32 " \
        "{%0,%1,%2,%3}, {%4,%5,%6,%7}, {%8,%9}, {%0,%1,%2,%3};" \
        : "+f"((c)[0]), "+f"((c)[1]), "+f"((c)[2]), "+f"((c)[3]) \
        : "r"(a0), "r"(a1), "r"(a2), "r"(a3), "r"(b0), "r"(b1))

// ================= unified fp16 2-term GEMM ==================
// C[m,n] = sum_k (Ah+Al)[m,k] * B[n,k]; fp32 accum.
// Block 128x128, 4 warps of 64x64, K chunk 32, 3-stage cp.async (1 sync/chunk).
// blockIdx.x >= nxMain selects the secondary problem (B2, C2, Ns=256).
#define RB    80                        // smem row bytes: 32 halves (64B) + 16B pad
#define TILE  (128 * RB)                // 10240 B per operand tile
#define STG3  (3 * TILE)                // Ah,Al,B per stage = 30720 B
#define NCH   (KKc / 32)                // 64 chunks

__global__ __launch_bounds__(128, 2)
void f16_gemm(const __half* __restrict__ Ah, const __half* __restrict__ Al,
              const __half* __restrict__ B, float* __restrict__ C,
              int NsMain, int nxMain,
              const __half* __restrict__ B2, float* __restrict__ C2)
{
    extern __shared__ char smem[];
    const uint32_t sb = smem_u32(smem);
    const int tid  = threadIdx.x;
    const int wid  = tid >> 5;
    const int lane = tid & 31;
    const int m0 = blockIdx.y * 128;
    const int wm = (wid & 1) * 64;
    const int wn = (wid >> 1) * 64;

    const __half* BS; float* CS; int n0, Ns;
    if ((int)blockIdx.x < nxMain) {
        BS = B;  CS = C;  n0 = blockIdx.x * 128;            Ns = NsMain;
    } else {
        BS = B2; CS = C2; n0 = (blockIdx.x - nxMain) * 128; Ns = 256;
    }

    const int g = lane >> 3, r = lane & 7;
    uint32_t aOff[4], bOff[4];
    #pragma unroll
    for (int mt = 0; mt < 4; mt++)
        aOff[mt] = (uint32_t)((wm + mt * 16 + (g & 1) * 8 + r) * RB + (g >> 1) * 16);
    #pragma unroll
    for (int nt2 = 0; nt2 < 4; nt2++)
        bOff[nt2] = (uint32_t)(2 * TILE + (wn + nt2 * 16 + (g >> 1) * 8 + r) * RB + (g & 1) * 16);

    float acc[4][8][4];
    #pragma unroll
    for (int i = 0; i < 4; i++)
        #pragma unroll
        for (int j = 0; j < 8; j++)
            #pragma unroll
            for (int v = 0; v < 4; v++) acc[i][j][v] = 0.f;

    const __half* tp[3] = { Ah + (size_t)m0 * KKc, Al + (size_t)m0 * KKc,
                            BS + (size_t)n0 * KKc };

    auto load_stage = [&](int c, int st) {
        const uint32_t base = sb + st * STG3;
        #pragma unroll
        for (int t = 0; t < 3; t++) {
            const __half* src = tp[t] + c * 32;
            #pragma unroll
            for (int i = 0; i < 4; i++) {
                const int idx = tid + i * 128;       // 0..511
                const int row = idx >> 2;
                const int ch  = idx & 3;
                cp_async16(base + t * TILE + row * RB + ch * 16,
                           src + (size_t)row * KKc + ch * 8);
            }
        }
        CP_COMMIT();
    };

    load_stage(0, 0);
    load_stage(1, 1);

    for (int c = 0; c < NCH; c++) {
        if (c + 1 < NCH) CP_WAIT1(); else CP_WAIT0();
        __syncthreads();
        if (c + 2 < NCH) load_stage(c + 2, (c + 2) % 3);

        const uint32_t stb = sb + (c % 3) * STG3;
        #pragma unroll
        for (int ks = 0; ks < 2; ks++) {
            const uint32_t ko = ks * 32;
            uint32_t ah[4][4], bh[4][4], al[4][4];

            #pragma unroll
            for (int mt = 0; mt < 4; mt++)
                LDSM4(ah[mt][0], ah[mt][1], ah[mt][2], ah[mt][3], stb + aOff[mt] + ko);
            #pragma unroll
            for (int nt2 = 0; nt2 < 4; nt2++)
                LDSM4(bh[nt2][0], bh[nt2][1], bh[nt2][2], bh[nt2][3], stb + bOff[nt2] + ko);
            #pragma unroll
            for (int mt = 0; mt < 4; mt++)
                #pragma unroll
                for (int nt = 0; nt < 8; nt++) {
                    const uint32_t* bb = &bh[nt >> 1][(nt & 1) * 2];
                    MMA_F16(acc[mt][nt], ah[mt][0], ah[mt][1], ah[mt][2], ah[mt][3], bb[0], bb[1]);
                }

            #pragma unroll
            for (int mt = 0; mt < 4; mt++)
                LDSM4(al[mt][0], al[mt][1], al[mt][2], al[mt][3], stb + TILE + aOff[mt] + ko);
            #pragma unroll
            for (int mt = 0; mt < 4; mt++)
                #pragma unroll
                for (int nt = 0; nt < 8; nt++) {
                    const uint32_t* bb = &bh[nt >> 1][(nt & 1) * 2];
                    MMA_F16(acc[mt][nt], al[mt][0], al[mt][1], al[mt][2], al[mt][3], bb[0], bb[1]);
                }
        }
    }

    #pragma unroll
    for (int mt = 0; mt < 4; mt++) {
        const int m = m0 + wm + mt * 16 + (lane >> 2);
        #pragma unroll
        for (int nt = 0; nt < 8; nt++) {
            const int n = n0 + wn + nt * 8 + (lane & 3) * 2;
            *(float2*)(CS + (size_t)m * Ns + n)       = make_float2(acc[mt][nt][0], acc[mt][nt][1]);
            *(float2*)(CS + (size_t)(m + 8) * Ns + n) = make_float2(acc[mt][nt][2], acc[mt][nt][3]);
        }
    }
}

// ---------------- fp32 -> fp16 hi/lo split ----------------
__global__ void split_f16(const float4* __restrict__ src,
                          uint2* __restrict__ H, uint2* __restrict__ L, int n4)
{
    int i = blockIdx.x * blockDim.x + threadIdx.x;
    if (i >= n4) return;
    float4 v = src[i];
    __half h0 = __float2half_rn(v.x), h1 = __float2half_rn(v.y);
    __half h2 = __float2half_rn(v.z), h3 = __float2half_rn(v.w);
    __half l0 = __float2half_rn(v.x - __half2float(h0));
    __half l1 = __float2half_rn(v.y - __half2float(h1));
    __half l2 = __float2half_rn(v.z - __half2float(h2));
    __half l3 = __float2half_rn(v.w - __half2float(h3));
    __half2 ha = {h0, h1}, hb = {h2, h3}, la = {l0, l1}, lb = {l2, l3};
    H[i] = make_uint2(*(uint32_t*)&ha, *(uint32_t*)&hb);
    L[i] = make_uint2(*(uint32_t*)&la, *(uint32_t*)&lb);
}

// ---------------- fp32 -> fp16 (single, rn) ----------------
__global__ void cvt_f16(const float4* __restrict__ src, uint2* __restrict__ H, int n4)
{
    int i = blockIdx.x * blockDim.x + threadIdx.x;
    if (i >= n4) return;
    float4 v = src[i];
    __half2 a = __floats2half2_rn(v.x, v.y);
    __half2 b = __floats2half2_rn(v.z, v.w);
    H[i] = make_uint2(*(uint32_t*)&a, *(uint32_t*)&b);
}

// ---------------- theta RMS scale (per-row rsqrt only) ----------------
__global__ void rms_scale(const float* __restrict__ X, float* __restrict__ scale, int cols)
{
    const int row = blockIdx.x;
    const float* xr = X + (size_t)row * cols;
    float ss = 0.f;
    for (int c = threadIdx.x * 4; c < cols; c += blockDim.x * 4) {
        float4 v = *(const float4*)(xr + c);
        ss += v.x * v.x + v.y * v.y + v.z * v.z + v.w * v.w;
    }
    #pragma unroll
    for (int o = 16; o > 0; o >>= 1) ss += __shfl_xor_sync(0xffffffffu, ss, o);
    __shared__ float red[32];
    const int warp = threadIdx.x >> 5, lane = threadIdx.x & 31;
    if (lane == 0) red[warp] = ss;
    __syncthreads();
    if (warp == 0) {
        ss = (lane < (blockDim.x >> 5)) ? red[lane] : 0.f;
        #pragma unroll
        for (int o = 16; o > 0; o >>= 1) ss += __shfl_xor_sync(0xffffffffu, ss, o);
        if (lane == 0) scale[row] = rsqrtf(ss / (float)cols + EPSV);
    }
}

// ---------------- fused RMSNorm(phi) + sincos transpose ----------------
__global__ __launch_bounds__(192)
void phi_rms_sincos(const float* __restrict__ phi, float2* __restrict__ sc)
{
    const int row = blockIdx.x;            // b*4096 + t
    const int t   = row & (Tc - 1);
    const int b   = row >> 12;
    const int j   = threadIdx.x;           // 0..191
    const float v = phi[(size_t)row * 256 + j];

    float ss = v * v;
    #pragma unroll
    for (int o = 16; o > 0; o >>= 1) ss += __shfl_xor_sync(0xffffffffu, ss, o);
    __shared__ float red[6];
    const int warp = j >> 5, lane = j & 31;
    if (lane == 0) red[warp] = ss;
    __syncthreads();
    float tot = red[0] + red[1] + red[2] + red[3] + red[4] + red[5];
    const float rs = rsqrtf(tot / (float)LHc + EPSV);

    float s, c;
    sincosf(v * rs, &s, &c);
    const int l = j >> 4, h = j & 15;
    sc[((size_t)(b * Hc + h) * Lc + l) * Tc + t] = make_float2(c * INVSQRT2, s * INVSQRT2);
}

// ---------------- fused 12-level butterfly -> fp16 hi/lo ----------------
__global__ __launch_bounds__(512, 1)
void butterfly_fused(const float* __restrict__ theta, const float* __restrict__ tscale,
                     const float2* __restrict__ sc,
                     __half* __restrict__ Th, __half* __restrict__ Tl)
{
    extern __shared__ float th[];   // [4096][9]
    const int ds  = blockIdx.x;     // 0..15
    const int h   = blockIdx.y;     // 0..15
    const int b   = blockIdx.z;     // 0..1
    const int tid = threadIdx.x;
    const int cb  = h * 128 + ds * 8;
    const size_t rowbase = (size_t)b * Tc;

    #pragma unroll
    for (int k = 0; k < 8; k++) {
        const int t = tid + k * 512;
        const float scl = tscale[rowbase + t];
        const float* g = theta + (rowbase + t) * Dc + cb;
        float4 v0 = *(const float4*)g;
        float4 v1 = *(const float4*)(g + 4);
        float* s = &th[t * 9];
        s[0] = v0.x * scl; s[1] = v0.y * scl; s[2] = v0.z * scl; s[3] = v0.w * scl;
        s[4] = v1.x * scl; s[5] = v1.y * scl; s[6] = v1.z * scl; s[7] = v1.w * scl;
    }
    __syncthreads();

    const float2* scb = sc + (size_t)(b * Hc + h) * Lc * Tc;
    for (int l = 0; l < Lc; l++) {
        const int step = 1 << l;
        float2 w[8];
        #pragma unroll
        for (int k = 0; k < 8; k++) w[k] = scb[l * Tc + tid + k * 512];

        #pragma unroll
        for (int jh = 0; jh < 8; jh += 4) {
            float o[8][4];
            #pragma unroll
            for (int k = 0; k < 8; k++) {
                const int t = tid + k * 512;
                #pragma unroll
                for (int j = 0; j < 4; j++) {
                    float cur  = th[t * 9 + jh + j];
                    float prev = (t >= step) ? th[(t - step) * 9 + jh + j] : 0.f;
                    o[k][j] = fmaf(w[k].x, cur, w[k].y * prev);
                }
            }
            __syncthreads();
            #pragma unroll
            for (int k = 0; k < 8; k++) {
                const int t = tid + k * 512;
                #pragma unroll
                for (int j = 0; j < 4; j++) th[t * 9 + jh + j] = o[k][j];
            }
            __syncthreads();
        }
    }

    #pragma unroll
    for (int k = 0; k < 8; k++) {
        const int t = tid + k * 512;
        const float* s = &th[t * 9];
        __half hh[8], ll[8];
        #pragma unroll
        for (int j = 0; j < 8; j++) {
            float v = s[j];
            hh[j] = __float2half_rn(v);
            ll[j] = __float2half_rn(v - __half2float(hh[j]));
        }
        *(uint4*)(Th + (rowbase + t) * Dc + cb) = *(uint4*)hh;
        *(uint4*)(Tl + (rowbase + t) * Dc + cb) = *(uint4*)ll;
    }
}

// ---------------- launcher ----------------
extern "C" void kernel_launch(void* const* d_in, const int* in_sizes, int n_in,
                              void* d_out, int out_size)
{
    const float* x     = (const float*)d_in[0];
    const float* W_tok = (const float*)d_in[1];
    const float* W_lvl = (const float*)d_in[2];
    const float* W_out = (const float*)d_in[3];
    float* out = (float*)d_out;

    __half *xh, *xl, *wth, *woh, *wlh, *thh, *thl;
    float *theta, *phi, *tscale; float2* sc;
    cudaGetSymbolAddress((void**)&xh,  g_xh);   cudaGetSymbolAddress((void**)&xl,  g_xl);
    cudaGetSymbolAddress((void**)&wth, g_wth);  cudaGetSymbolAddress((void**)&woh, g_woh);
    cudaGetSymbolAddress((void**)&wlh, g_wlh);
    cudaGetSymbolAddress((void**)&thh, g_thh);  cudaGetSymbolAddress((void**)&thl, g_thl);
    cudaGetSymbolAddress((void**)&theta,  g_theta);
    cudaGetSymbolAddress((void**)&phi,    g_phi);
    cudaGetSymbolAddress((void**)&tscale, g_tscale);
    cudaGetSymbolAddress((void**)&sc,     g_sc);

    const int SMEM_GEMM = 3 * STG3;             // 92160
    const int SMEM_BFLY = 4096 * 9 * 4;         // 147456
    cudaFuncSetAttribute(f16_gemm, cudaFuncAttributeMaxDynamicSharedMemorySize, SMEM_GEMM);
    cudaFuncSetAttribute(butterfly_fused, cudaFuncAttributeMaxDynamicSharedMemorySize, SMEM_BFLY);

    // 1) operand conversions
    split_f16<<<(Mc * Dc / 4 + 255) / 256, 256>>>((const float4*)x, (uint2*)xh, (uint2*)xl, Mc * Dc / 4);
    cvt_f16<<<(Dc * Dc / 4 + 255) / 256, 256>>>((const float4*)W_tok, (uint2*)wth, Dc * Dc / 4);
    cvt_f16<<<(Dc * Dc / 4 + 255) / 256, 256>>>((const float4*)W_out, (uint2*)woh, Dc * Dc / 4);
    cvt_f16<<<(LHc * Dc / 4 + 255) / 256, 256>>>((const float4*)W_lvl, (uint2*)wlh, LHc * Dc / 4);

    // 2) merged GEMM: theta = x@W_tok^T (bx 0..15), phi = x@W_lvl^T (bx 16..17)
    f16_gemm<<<dim3(18, Mc / 128), 128, SMEM_GEMM>>>(xh, xl, wth, theta, Dc, 16,
                                                     wlh, phi);

    // 3) norms
    rms_scale<<<Mc, 256>>>(theta, tscale, Dc);
    phi_rms_sincos<<<Mc, 192>>>(phi, sc);

    // 4) fused butterfly (12 levels, applies tscale), emits fp16 hi/lo
    butterfly_fused<<<dim3(16, Hc, 2), 512, SMEM_BFLY>>>(theta, tscale, sc, thh, thl);

    // 5) y = theta @ W_out^T
    f16_gemm<<<dim3(16, Mc / 128), 128, SMEM_GEMM>>>(thh, thl, woh, out, Dc, 16,
                                                     nullptr, nullptr);
}

// round 10
// speedup vs baseline: 4.1598x; 1.1690x over previous
#include <cuda_runtime.h>
#include <cuda_fp16.h>
#include <cstdint>
#include <math.h>

// ---------------- problem shapes (fixed) ----------------
#define Tc   4096
#define Dc   2048
#define Hc   16
#define Lc   12
#define LHc  192
#define Mc   8192          // B*T
#define KKc  2048          // GEMM K
#define EPSV 1.1920929e-07f
#define INVSQRT2 0.70710678118654752440f

// ---------------- scratch (static device globals; zero-initialized) ----------
__device__ __half g_xh [(size_t)Mc * Dc];      // x fp16 hi
__device__ __half g_xl [(size_t)Mc * Dc];      // x fp16 lo
__device__ __half g_wth[(size_t)Dc * Dc];      // W_tok fp16
__device__ __half g_woh[(size_t)Dc * Dc];      // W_out fp16
__device__ __half g_wlh[(size_t)256 * Dc];     // W_lvl fp16 hi, padded 192->256 rows
__device__ __half g_wll[(size_t)256 * Dc];     // W_lvl fp16 lo
__device__ __half g_thh[(size_t)Mc * Dc];      // theta fp16 (single)
__device__ float g_theta [(size_t)Mc * Dc];
__device__ float g_phi   [(size_t)Mc * 256];   // padded cols
__device__ float g_tscale[(size_t)Mc];
__device__ float2 g_sc   [(size_t)2 * Hc * Lc * Tc];

// ---------------- PTX helpers ----------------
__device__ __forceinline__ uint32_t smem_u32(const void* p) {
    uint32_t a;
    asm("{ .reg .u64 t; cvta.to.shared.u64 t, %1; cvt.u32.u64 %0, t; }" : "=r"(a) : "l"(p));
    return a;
}
__device__ __forceinline__ void cp_async16(uint32_t s, const void* g) {
    asm volatile("cp.async.cg.shared.global [%0], [%1], 16;" :: "r"(s), "l"(g));
}
#define CP_COMMIT() asm volatile("cp.async.commit_group;" ::: "memory")
#define CP_WAIT1()  asm volatile("cp.async.wait_group 1;" ::: "memory")
#define CP_WAIT0()  asm volatile("cp.async.wait_group 0;" ::: "memory")

#define LDSM4(d0,d1,d2,d3,a) \
    asm volatile("ldmatrix.sync.aligned.m8n8.x4.shared.b16 {%0,%1,%2,%3}, [%4];" \
        : "=r"(d0), "=r"(d1), "=r"(d2), "=r"(d3) : "r"(a))

#define MMA_F16(c, a0,a1,a2,a3, b0,b1) \
    asm volatile("mma.sync.aligned.m16n8k16.row.col.f32.f16.f16.f32 " \
        "{%0,%1,%2,%3}, {%4,%5,%6,%7}, {%8,%9}, {%0,%1,%2,%3};" \
        : "+f"((c)[0]), "+f"((c)[1]), "+f"((c)[2]), "+f"((c)[3]) \
        : "r"(a0), "r"(a1), "r"(a2), "r"(a3), "r"(b0), "r"(b1))

#define RB    80                        // smem row bytes: 32 halves (64B) + 16B pad
#define TILE  (128 * RB)                // 10240 B per operand tile
#define STG3  (3 * TILE)                // 30720 (primary stage: Ah,Al,B)
#define STG4  (4 * TILE)                // 40960 (secondary stage: Ah,Al,Bh,Bl)
#define STG2  (2 * TILE)                // 20480 (GEMM3 stage: A,B)
#define NCH   (KKc / 32)                // 64 chunks

// ============== merged GEMM: theta (2-pass) + phi (3-pass) ==================
// primary (bx<16):  C = (Ah+Al) @ B^T          (3-stage pipeline)
// secondary (bx>=16): C2 = (Ah+Al) @ (Bh2+Bl2)^T approx AhBh+AlBh+AhBl (2-stage)
__global__ __launch_bounds__(128, 2)
void f16_gemm_main(const __half* __restrict__ Ah, const __half* __restrict__ Al,
                   const __half* __restrict__ B, float* __restrict__ C,
                   const __half* __restrict__ Bh2, const __half* __restrict__ Bl2,
                   float* __restrict__ C2)
{
    extern __shared__ char smem[];
    const uint32_t sb = smem_u32(smem);
    const int tid  = threadIdx.x;
    const int wid  = tid >> 5;
    const int lane = tid & 31;
    const int m0 = blockIdx.y * 128;
    const int wm = (wid & 1) * 64;
    const int wn = (wid >> 1) * 64;

    const int g = lane >> 3, r = lane & 7;
    uint32_t aOff[4], bOff[4];
    #pragma unroll
    for (int mt = 0; mt < 4; mt++)
        aOff[mt] = (uint32_t)((wm + mt * 16 + (g & 1) * 8 + r) * RB + (g >> 1) * 16);
    #pragma unroll
    for (int nt2 = 0; nt2 < 4; nt2++)
        bOff[nt2] = (uint32_t)(2 * TILE + (wn + nt2 * 16 + (g >> 1) * 8 + r) * RB + (g & 1) * 16);

    float acc[4][8][4];
    #pragma unroll
    for (int i = 0; i < 4; i++)
        #pragma unroll
        for (int j = 0; j < 8; j++)
            #pragma unroll
            for (int v = 0; v < 4; v++) acc[i][j][v] = 0.f;

    float* CS; int n0, Ns;

    if ((int)blockIdx.x < 16) {
        // ---------------- primary: 3-stage, 2 passes ----------------
        CS = C; n0 = blockIdx.x * 128; Ns = Dc;
        const __half* tp[3] = { Ah + (size_t)m0 * KKc, Al + (size_t)m0 * KKc,
                                B + (size_t)n0 * KKc };

        auto load_stage = [&](int c, int st) {
            const uint32_t base = sb + st * STG3;
            #pragma unroll
            for (int t = 0; t < 3; t++) {
                const __half* src = tp[t] + c * 32;
                #pragma unroll
                for (int i = 0; i < 4; i++) {
                    const int idx = tid + i * 128;
                    const int row = idx >> 2;
                    const int ch  = idx & 3;
                    cp_async16(base + t * TILE + row * RB + ch * 16,
                               src + (size_t)row * KKc + ch * 8);
                }
            }
            CP_COMMIT();
        };

        load_stage(0, 0);
        load_stage(1, 1);

        for (int c = 0; c < NCH; c++) {
            if (c + 1 < NCH) CP_WAIT1(); else CP_WAIT0();
            __syncthreads();
            if (c + 2 < NCH) load_stage(c + 2, (c + 2) % 3);

            const uint32_t stb = sb + (c % 3) * STG3;
            #pragma unroll
            for (int ks = 0; ks < 2; ks++) {
                const uint32_t ko = ks * 32;
                uint32_t ah[4][4], bh[4][4], al[4][4];

                #pragma unroll
                for (int mt = 0; mt < 4; mt++)
                    LDSM4(ah[mt][0], ah[mt][1], ah[mt][2], ah[mt][3], stb + aOff[mt] + ko);
                #pragma unroll
                for (int nt2 = 0; nt2 < 4; nt2++)
                    LDSM4(bh[nt2][0], bh[nt2][1], bh[nt2][2], bh[nt2][3], stb + bOff[nt2] + ko);
                #pragma unroll
                for (int mt = 0; mt < 4; mt++)
                    #pragma unroll
                    for (int nt = 0; nt < 8; nt++) {
                        const uint32_t* bb = &bh[nt >> 1][(nt & 1) * 2];
                        MMA_F16(acc[mt][nt], ah[mt][0], ah[mt][1], ah[mt][2], ah[mt][3], bb[0], bb[1]);
                    }

                #pragma unroll
                for (int mt = 0; mt < 4; mt++)
                    LDSM4(al[mt][0], al[mt][1], al[mt][2], al[mt][3], stb + TILE + aOff[mt] + ko);
                #pragma unroll
                for (int mt = 0; mt < 4; mt++)
                    #pragma unroll
                    for (int nt = 0; nt < 8; nt++) {
                        const uint32_t* bb = &bh[nt >> 1][(nt & 1) * 2];
                        MMA_F16(acc[mt][nt], al[mt][0], al[mt][1], al[mt][2], al[mt][3], bb[0], bb[1]);
                    }
            }
        }
    } else {
        // ---------------- secondary (phi): 2-stage, 3 passes ----------------
        CS = C2; n0 = ((int)blockIdx.x - 16) * 128; Ns = 256;
        const __half* tp[4] = { Ah + (size_t)m0 * KKc, Al + (size_t)m0 * KKc,
                                Bh2 + (size_t)n0 * KKc, Bl2 + (size_t)n0 * KKc };

        auto load_stage4 = [&](int c, int st) {
            const uint32_t base = sb + st * STG4;
            #pragma unroll
            for (int i = 0; i < 16; i++) {
                const int idx = tid + i * 128;       // 0..2047
                const int t   = idx >> 9;
                const int rem = idx & 511;
                const int row = rem >> 2;
                const int ch  = rem & 3;
                cp_async16(base + t * TILE + row * RB + ch * 16,
                           tp[t] + (size_t)row * KKc + c * 32 + ch * 8);
            }
            CP_COMMIT();
        };

        load_stage4(0, 0);

        for (int c = 0; c < NCH; c++) {
            if (c + 1 < NCH) { load_stage4(c + 1, (c + 1) & 1); CP_WAIT1(); }
            else             { CP_WAIT0(); }
            __syncthreads();

            const uint32_t stb = sb + (c & 1) * STG4;
            #pragma unroll
            for (int ks = 0; ks < 2; ks++) {
                const uint32_t ko = ks * 32;
                uint32_t ah[4][4], bh[4][4], xx[4][4];

                #pragma unroll
                for (int mt = 0; mt < 4; mt++)
                    LDSM4(ah[mt][0], ah[mt][1], ah[mt][2], ah[mt][3], stb + aOff[mt] + ko);
                #pragma unroll
                for (int nt2 = 0; nt2 < 4; nt2++)
                    LDSM4(bh[nt2][0], bh[nt2][1], bh[nt2][2], bh[nt2][3], stb + bOff[nt2] + ko);
                #pragma unroll
                for (int mt = 0; mt < 4; mt++)
                    #pragma unroll
                    for (int nt = 0; nt < 8; nt++) {
                        const uint32_t* bb = &bh[nt >> 1][(nt & 1) * 2];
                        MMA_F16(acc[mt][nt], ah[mt][0], ah[mt][1], ah[mt][2], ah[mt][3], bb[0], bb[1]);
                    }

                #pragma unroll
                for (int mt = 0; mt < 4; mt++)
                    LDSM4(xx[mt][0], xx[mt][1], xx[mt][2], xx[mt][3], stb + TILE + aOff[mt] + ko);
                #pragma unroll
                for (int mt = 0; mt < 4; mt++)
                    #pragma unroll
                    for (int nt = 0; nt < 8; nt++) {
                        const uint32_t* bb = &bh[nt >> 1][(nt & 1) * 2];
                        MMA_F16(acc[mt][nt], xx[mt][0], xx[mt][1], xx[mt][2], xx[mt][3], bb[0], bb[1]);
                    }

                #pragma unroll
                for (int nt2 = 0; nt2 < 4; nt2++)
                    LDSM4(xx[nt2][0], xx[nt2][1], xx[nt2][2], xx[nt2][3], stb + TILE + bOff[nt2] + ko);
                #pragma unroll
                for (int mt = 0; mt < 4; mt++)
                    #pragma unroll
                    for (int nt = 0; nt < 8; nt++) {
                        const uint32_t* bb = &xx[nt >> 1][(nt & 1) * 2];
                        MMA_F16(acc[mt][nt], ah[mt][0], ah[mt][1], ah[mt][2], ah[mt][3], bb[0], bb[1]);
                    }
            }
            __syncthreads();
        }
    }

    #pragma unroll
    for (int mt = 0; mt < 4; mt++) {
        const int m = m0 + wm + mt * 16 + (lane >> 2);
        #pragma unroll
        for (int nt = 0; nt < 8; nt++) {
            const int n = n0 + wn + nt * 8 + (lane & 3) * 2;
            *(float2*)(CS + (size_t)m * Ns + n)       = make_float2(acc[mt][nt][0], acc[mt][nt][1]);
            *(float2*)(CS + (size_t)(m + 8) * Ns + n) = make_float2(acc[mt][nt][2], acc[mt][nt][3]);
        }
    }
}

// ================= GEMM3: single-pass fp16 ==================
__global__ __launch_bounds__(128, 2)
void f16_gemm1(const __half* __restrict__ A, const __half* __restrict__ B,
               float* __restrict__ C)
{
    extern __shared__ char smem[];
    const uint32_t sb = smem_u32(smem);
    const int tid  = threadIdx.x;
    const int wid  = tid >> 5;
    const int lane = tid & 31;
    const int m0 = blockIdx.y * 128;
    const int n0 = blockIdx.x * 128;
    const int wm = (wid & 1) * 64;
    const int wn = (wid >> 1) * 64;

    const int g = lane >> 3, r = lane & 7;
    uint32_t aOff[4], bOff[4];
    #pragma unroll
    for (int mt = 0; mt < 4; mt++)
        aOff[mt] = (uint32_t)((wm + mt * 16 + (g & 1) * 8 + r) * RB + (g >> 1) * 16);
    #pragma unroll
    for (int nt2 = 0; nt2 < 4; nt2++)
        bOff[nt2] = (uint32_t)(TILE + (wn + nt2 * 16 + (g >> 1) * 8 + r) * RB + (g & 1) * 16);

    float acc[4][8][4];
    #pragma unroll
    for (int i = 0; i < 4; i++)
        #pragma unroll
        for (int j = 0; j < 8; j++)
            #pragma unroll
            for (int v = 0; v < 4; v++) acc[i][j][v] = 0.f;

    const __half* tp[2] = { A + (size_t)m0 * KKc, B + (size_t)n0 * KKc };

    auto load_stage = [&](int c, int st) {
        const uint32_t base = sb + st * STG2;
        #pragma unroll
        for (int t = 0; t < 2; t++) {
            const __half* src = tp[t] + c * 32;
            #pragma unroll
            for (int i = 0; i < 4; i++) {
                const int idx = tid + i * 128;
                const int row = idx >> 2;
                const int ch  = idx & 3;
                cp_async16(base + t * TILE + row * RB + ch * 16,
                           src + (size_t)row * KKc + ch * 8);
            }
        }
        CP_COMMIT();
    };

    load_stage(0, 0);
    load_stage(1, 1);

    for (int c = 0; c < NCH; c++) {
        if (c + 1 < NCH) CP_WAIT1(); else CP_WAIT0();
        __syncthreads();
        if (c + 2 < NCH) load_stage(c + 2, (c + 2) % 3);

        const uint32_t stb = sb + (c % 3) * STG2;
        #pragma unroll
        for (int ks = 0; ks < 2; ks++) {
            const uint32_t ko = ks * 32;
            uint32_t ah[4][4], bh[4][4];
            #pragma unroll
            for (int mt = 0; mt < 4; mt++)
                LDSM4(ah[mt][0], ah[mt][1], ah[mt][2], ah[mt][3], stb + aOff[mt] + ko);
            #pragma unroll
            for (int nt2 = 0; nt2 < 4; nt2++)
                LDSM4(bh[nt2][0], bh[nt2][1], bh[nt2][2], bh[nt2][3], stb + bOff[nt2] + ko);
            #pragma unroll
            for (int mt = 0; mt < 4; mt++)
                #pragma unroll
                for (int nt = 0; nt < 8; nt++) {
                    const uint32_t* bb = &bh[nt >> 1][(nt & 1) * 2];
                    MMA_F16(acc[mt][nt], ah[mt][0], ah[mt][1], ah[mt][2], ah[mt][3], bb[0], bb[1]);
                }
        }
    }

    #pragma unroll
    for (int mt = 0; mt < 4; mt++) {
        const int m = m0 + wm + mt * 16 + (lane >> 2);
        #pragma unroll
        for (int nt = 0; nt < 8; nt++) {
            const int n = n0 + wn + nt * 8 + (lane & 3) * 2;
            *(float2*)(C + (size_t)m * Dc + n)       = make_float2(acc[mt][nt][0], acc[mt][nt][1]);
            *(float2*)(C + (size_t)(m + 8) * Dc + n) = make_float2(acc[mt][nt][2], acc[mt][nt][3]);
        }
    }
}

// ---------------- fp32 -> fp16 hi/lo split ----------------
__global__ void split_f16(const float4* __restrict__ src,
                          uint2* __restrict__ H, uint2* __restrict__ L, int n4)
{
    int i = blockIdx.x * blockDim.x + threadIdx.x;
    if (i >= n4) return;
    float4 v = src[i];
    __half h0 = __float2half_rn(v.x), h1 = __float2half_rn(v.y);
    __half h2 = __float2half_rn(v.z), h3 = __float2half_rn(v.w);
    __half l0 = __float2half_rn(v.x - __half2float(h0));
    __half l1 = __float2half_rn(v.y - __half2float(h1));
    __half l2 = __float2half_rn(v.z - __half2float(h2));
    __half l3 = __float2half_rn(v.w - __half2float(h3));
    __half2 ha = {h0, h1}, hb = {h2, h3}, la = {l0, l1}, lb = {l2, l3};
    H[i] = make_uint2(*(uint32_t*)&ha, *(uint32_t*)&hb);
    L[i] = make_uint2(*(uint32_t*)&la, *(uint32_t*)&lb);
}

// ---------------- fp32 -> fp16 (single, rn) ----------------
__global__ void cvt_f16(const float4* __restrict__ src, uint2* __restrict__ H, int n4)
{
    int i = blockIdx.x * blockDim.x + threadIdx.x;
    if (i >= n4) return;
    float4 v = src[i];
    __half2 a = __floats2half2_rn(v.x, v.y);
    __half2 b = __floats2half2_rn(v.z, v.w);
    H[i] = make_uint2(*(uint32_t*)&a, *(uint32_t*)&b);
}

// ---------------- theta RMS scale (per-row rsqrt only) ----------------
__global__ void rms_scale(const float* __restrict__ X, float* __restrict__ scale, int cols)
{
    const int row = blockIdx.x;
    const float* xr = X + (size_t)row * cols;
    float ss = 0.f;
    for (int c = threadIdx.x * 4; c < cols; c += blockDim.x * 4) {
        float4 v = *(const float4*)(xr + c);
        ss += v.x * v.x + v.y * v.y + v.z * v.z + v.w * v.w;
    }
    #pragma unroll
    for (int o = 16; o > 0; o >>= 1) ss += __shfl_xor_sync(0xffffffffu, ss, o);
    __shared__ float red[32];
    const int warp = threadIdx.x >> 5, lane = threadIdx.x & 31;
    if (lane == 0) red[warp] = ss;
    __syncthreads();
    if (warp == 0) {
        ss = (lane < (blockDim.x >> 5)) ? red[lane] : 0.f;
        #pragma unroll
        for (int o = 16; o > 0; o >>= 1) ss += __shfl_xor_sync(0xffffffffu, ss, o);
        if (lane == 0) scale[row] = rsqrtf(ss / (float)cols + EPSV);
    }
}

// ---------------- fused RMSNorm(phi) + sincos transpose ----------------
__global__ __launch_bounds__(192)
void phi_rms_sincos(const float* __restrict__ phi, float2* __restrict__ sc)
{
    const int row = blockIdx.x;            // b*4096 + t
    const int t   = row & (Tc - 1);
    const int b   = row >> 12;
    const int j   = threadIdx.x;           // 0..191
    const float v = phi[(size_t)row * 256 + j];

    float ss = v * v;
    #pragma unroll
    for (int o = 16; o > 0; o >>= 1) ss += __shfl_xor_sync(0xffffffffu, ss, o);
    __shared__ float red[6];
    const int warp = j >> 5, lane = j & 31;
    if (lane == 0) red[warp] = ss;
    __syncthreads();
    float tot = red[0] + red[1] + red[2] + red[3] + red[4] + red[5];
    const float rs = rsqrtf(tot / (float)LHc + EPSV);

    float s, c;
    sincosf(v * rs, &s, &c);
    const int l = j >> 4, h = j & 15;
    sc[((size_t)(b * Hc + h) * Lc + l) * Tc + t] = make_float2(c * INVSQRT2, s * INVSQRT2);
}

// ---------------- fused 12-level butterfly -> fp16 ----------------
__global__ __launch_bounds__(512, 1)
void butterfly_fused(const float* __restrict__ theta, const float* __restrict__ tscale,
                     const float2* __restrict__ sc, __half* __restrict__ Th)
{
    extern __shared__ float th[];   // [4096][9]
    const int ds  = blockIdx.x;     // 0..15
    const int h   = blockIdx.y;     // 0..15
    const int b   = blockIdx.z;     // 0..1
    const int tid = threadIdx.x;
    const int cb  = h * 128 + ds * 8;
    const size_t rowbase = (size_t)b * Tc;

    #pragma unroll
    for (int k = 0; k < 8; k++) {
        const int t = tid + k * 512;
        const float scl = tscale[rowbase + t];
        const float* g = theta + (rowbase + t) * Dc + cb;
        float4 v0 = *(const float4*)g;
        float4 v1 = *(const float4*)(g + 4);
        float* s = &th[t * 9];
        s[0] = v0.x * scl; s[1] = v0.y * scl; s[2] = v0.z * scl; s[3] = v0.w * scl;
        s[4] = v1.x * scl; s[5] = v1.y * scl; s[6] = v1.z * scl; s[7] = v1.w * scl;
    }
    __syncthreads();

    const float2* scb = sc + (size_t)(b * Hc + h) * Lc * Tc;
    for (int l = 0; l < Lc; l++) {
        const int step = 1 << l;
        float2 w[8];
        #pragma unroll
        for (int k = 0; k < 8; k++) w[k] = scb[l * Tc + tid + k * 512];

        #pragma unroll
        for (int jh = 0; jh < 8; jh += 4) {
            float o[8][4];
            #pragma unroll
            for (int k = 0; k < 8; k++) {
                const int t = tid + k * 512;
                #pragma unroll
                for (int j = 0; j < 4; j++) {
                    float cur  = th[t * 9 + jh + j];
                    float prev = (t >= step) ? th[(t - step) * 9 + jh + j] : 0.f;
                    o[k][j] = fmaf(w[k].x, cur, w[k].y * prev);
                }
            }
            __syncthreads();
            #pragma unroll
            for (int k = 0; k < 8; k++) {
                const int t = tid + k * 512;
                #pragma unroll
                for (int j = 0; j < 4; j++) th[t * 9 + jh + j] = o[k][j];
            }
            __syncthreads();
        }
    }

    #pragma unroll
    for (int k = 0; k < 8; k++) {
        const int t = tid + k * 512;
        const float* s = &th[t * 9];
        __half hh[8];
        #pragma unroll
        for (int j = 0; j < 8; j++) hh[j] = __float2half_rn(s[j]);
        *(uint4*)(Th + (rowbase + t) * Dc + cb) = *(uint4*)hh;
    }
}

// ---------------- launcher ----------------
extern "C" void kernel_launch(void* const* d_in, const int* in_sizes, int n_in,
                              void* d_out, int out_size)
{
    const float* x     = (const float*)d_in[0];
    const float* W_tok = (const float*)d_in[1];
    const float* W_lvl = (const float*)d_in[2];
    const float* W_out = (const float*)d_in[3];
    float* out = (float*)d_out;

    __half *xh, *xl, *wth, *woh, *wlh, *wll, *thh;
    float *theta, *phi, *tscale; float2* sc;
    cudaGetSymbolAddress((void**)&xh,  g_xh);   cudaGetSymbolAddress((void**)&xl,  g_xl);
    cudaGetSymbolAddress((void**)&wth, g_wth);  cudaGetSymbolAddress((void**)&woh, g_woh);
    cudaGetSymbolAddress((void**)&wlh, g_wlh);  cudaGetSymbolAddress((void**)&wll, g_wll);
    cudaGetSymbolAddress((void**)&thh, g_thh);
    cudaGetSymbolAddress((void**)&theta,  g_theta);
    cudaGetSymbolAddress((void**)&phi,    g_phi);
    cudaGetSymbolAddress((void**)&tscale, g_tscale);
    cudaGetSymbolAddress((void**)&sc,     g_sc);

    const int SMEM_MAIN  = 3 * STG3;            // 92160 (>= 2*STG4 = 81920)
    const int SMEM_G3    = 3 * STG2;            // 61440
    const int SMEM_BFLY  = 4096 * 9 * 4;        // 147456
    cudaFuncSetAttribute(f16_gemm_main, cudaFuncAttributeMaxDynamicSharedMemorySize, SMEM_MAIN);
    cudaFuncSetAttribute(f16_gemm1, cudaFuncAttributeMaxDynamicSharedMemorySize, SMEM_G3);
    cudaFuncSetAttribute(butterfly_fused, cudaFuncAttributeMaxDynamicSharedMemorySize, SMEM_BFLY);

    // 1) operand conversions
    split_f16<<<(Mc * Dc / 4 + 255) / 256, 256>>>((const float4*)x, (uint2*)xh, (uint2*)xl, Mc * Dc / 4);
    cvt_f16<<<(Dc * Dc / 4 + 255) / 256, 256>>>((const float4*)W_tok, (uint2*)wth, Dc * Dc / 4);
    cvt_f16<<<(Dc * Dc / 4 + 255) / 256, 256>>>((const float4*)W_out, (uint2*)woh, Dc * Dc / 4);
    split_f16<<<(LHc * Dc / 4 + 255) / 256, 256>>>((const float4*)W_lvl, (uint2*)wlh, (uint2*)wll, LHc * Dc / 4);

    // 2) merged GEMM: theta (bx 0..15, 2-pass) + phi (bx 16..17, 3-pass)
    f16_gemm_main<<<dim3(18, Mc / 128), 128, SMEM_MAIN>>>(xh, xl, wth, theta, wlh, wll, phi);

    // 3) norms
    rms_scale<<<Mc, 256>>>(theta, tscale, Dc);
    phi_rms_sincos<<<Mc, 192>>>(phi, sc);

    // 4) fused butterfly (12 levels, applies tscale), emits fp16 theta
    butterfly_fused<<<dim3(16, Hc, 2), 512, SMEM_BFLY>>>(theta, tscale, sc, thh);

    // 5) y = theta @ W_out^T  (single-pass fp16)
    f16_gemm1<<<dim3(16, Mc / 128), 128, SMEM_G3>>>(thh, woh, out);
}

// round 11
// speedup vs baseline: 4.9498x; 1.1899x over previous
#include <cuda_runtime.h>
#include <cuda_fp16.h>
#include <cstdint>
#include <math.h>

// ---------------- problem shapes (fixed) ----------------
#define Tc   4096
#define Dc   2048
#define Hc   16
#define Lc   12
#define LHc  192
#define Mc   8192          // B*T
#define KKc  2048          // GEMM K
#define EPSV 1.1920929e-07f
#define INVSQRT2 0.70710678118654752440f

// ---------------- scratch (static device globals; zero-initialized) ----------
__device__ __half g_xh [(size_t)Mc * Dc];      // x fp16 hi
__device__ __half g_xl [(size_t)Mc * Dc];      // x fp16 lo (phi path only)
__device__ __half g_wth[(size_t)Dc * Dc];      // W_tok fp16
__device__ __half g_woh[(size_t)Dc * Dc];      // W_out fp16
__device__ __half g_wlh[(size_t)256 * Dc];     // W_lvl fp16 hi, padded 192->256 rows
__device__ __half g_wll[(size_t)256 * Dc];     // W_lvl fp16 lo
__device__ __half g_thh[(size_t)Mc * Dc];      // theta fp16 (single)
__device__ float g_theta [(size_t)Mc * Dc];
__device__ float g_phi   [(size_t)Mc * 256];   // padded cols
__device__ float g_tscale[(size_t)Mc];
__device__ float2 g_sc   [(size_t)2 * Hc * Lc * Tc];

// ---------------- PTX helpers ----------------
__device__ __forceinline__ uint32_t smem_u32(const void* p) {
    uint32_t a;
    asm("{ .reg .u64 t; cvta.to.shared.u64 t, %1; cvt.u32.u64 %0, t; }" : "=r"(a) : "l"(p));
    return a;
}
__device__ __forceinline__ void cp_async16(uint32_t s, const void* g) {
    asm volatile("cp.async.cg.shared.global [%0], [%1], 16;" :: "r"(s), "l"(g));
}
#define CP_COMMIT() asm volatile("cp.async.commit_group;" ::: "memory")
#define CP_WAIT1()  asm volatile("cp.async.wait_group 1;" ::: "memory")
#define CP_WAIT0()  asm volatile("cp.async.wait_group 0;" ::: "memory")

#define LDSM4(d0,d1,d2,d3,a) \
    asm volatile("ldmatrix.sync.aligned.m8n8.x4.shared.b16 {%0,%1,%2,%3}, [%4];" \
        : "=r"(d0), "=r"(d1), "=r"(d2), "=r"(d3) : "r"(a))

#define MMA_F16(c, a0,a1,a2,a3, b0,b1) \
    asm volatile("mma.sync.aligned.m16n8k16.row.col.f32.f16.f16.f32 " \
        "{%0,%1,%2,%3}, {%4,%5,%6,%7}, {%8,%9}, {%0,%1,%2,%3};" \
        : "+f"((c)[0]), "+f"((c)[1]), "+f"((c)[2]), "+f"((c)[3]) \
        : "r"(a0), "r"(a1), "r"(a2), "r"(a3), "r"(b0), "r"(b1))

#define RB    80                        // smem row bytes: 32 halves (64B) + 16B pad
#define TILE  (128 * RB)                // 10240 B per operand tile
#define STG2  (2 * TILE)                // 20480 (single-pass stage: A,B)
#define STG4  (4 * TILE)                // 40960 (phi stage: Ah,Al,Bh,Bl)
#define NCH   (KKc / 32)                // 64 chunks

// ============== merged GEMM: theta (1-pass) + phi (3-pass) ==================
// primary (bx<16):   C  = Ah @ B^T                       (3-stage, 2 tiles)
// secondary (bx>=16): C2 = AhBh2 + AlBh2 + AhBl2          (2-stage, 4 tiles)
__global__ __launch_bounds__(128, 2)
void f16_gemm_main(const __half* __restrict__ Ah, const __half* __restrict__ Al,
                   const __half* __restrict__ B, float* __restrict__ C,
                   const __half* __restrict__ Bh2, const __half* __restrict__ Bl2,
                   float* __restrict__ C2)
{
    extern __shared__ char smem[];
    const uint32_t sb = smem_u32(smem);
    const int tid  = threadIdx.x;
    const int wid  = tid >> 5;
    const int lane = tid & 31;
    const int m0 = blockIdx.y * 128;
    const int wm = (wid & 1) * 64;
    const int wn = (wid >> 1) * 64;
    const bool primary = (int)blockIdx.x < 16;

    const int g = lane >> 3, r = lane & 7;
    const int bTile = primary ? 1 : 2;      // B tile index within stage
    uint32_t aOff[4], bOff[4];
    #pragma unroll
    for (int mt = 0; mt < 4; mt++)
        aOff[mt] = (uint32_t)((wm + mt * 16 + (g & 1) * 8 + r) * RB + (g >> 1) * 16);
    #pragma unroll
    for (int nt2 = 0; nt2 < 4; nt2++)
        bOff[nt2] = (uint32_t)(bTile * TILE + (wn + nt2 * 16 + (g >> 1) * 8 + r) * RB + (g & 1) * 16);

    float acc[4][8][4];
    #pragma unroll
    for (int i = 0; i < 4; i++)
        #pragma unroll
        for (int j = 0; j < 8; j++)
            #pragma unroll
            for (int v = 0; v < 4; v++) acc[i][j][v] = 0.f;

    float* CS; int n0, Ns;

    if (primary) {
        // ---------------- theta: 3-stage, 1 pass, 2 tiles ----------------
        CS = C; n0 = blockIdx.x * 128; Ns = Dc;
        const __half* tp[2] = { Ah + (size_t)m0 * KKc, B + (size_t)n0 * KKc };

        auto load_stage = [&](int c, int st) {
            const uint32_t base = sb + st * STG2;
            #pragma unroll
            for (int t = 0; t < 2; t++) {
                const __half* src = tp[t] + c * 32;
                #pragma unroll
                for (int i = 0; i < 4; i++) {
                    const int idx = tid + i * 128;
                    const int row = idx >> 2;
                    const int ch  = idx & 3;
                    cp_async16(base + t * TILE + row * RB + ch * 16,
                               src + (size_t)row * KKc + ch * 8);
                }
            }
            CP_COMMIT();
        };

        load_stage(0, 0);
        load_stage(1, 1);

        for (int c = 0; c < NCH; c++) {
            if (c + 1 < NCH) CP_WAIT1(); else CP_WAIT0();
            __syncthreads();
            if (c + 2 < NCH) load_stage(c + 2, (c + 2) % 3);

            const uint32_t stb = sb + (c % 3) * STG2;
            #pragma unroll
            for (int ks = 0; ks < 2; ks++) {
                const uint32_t ko = ks * 32;
                uint32_t ah[4][4], bh[4][4];
                #pragma unroll
                for (int mt = 0; mt < 4; mt++)
                    LDSM4(ah[mt][0], ah[mt][1], ah[mt][2], ah[mt][3], stb + aOff[mt] + ko);
                #pragma unroll
                for (int nt2 = 0; nt2 < 4; nt2++)
                    LDSM4(bh[nt2][0], bh[nt2][1], bh[nt2][2], bh[nt2][3], stb + bOff[nt2] + ko);
                #pragma unroll
                for (int mt = 0; mt < 4; mt++)
                    #pragma unroll
                    for (int nt = 0; nt < 8; nt++) {
                        const uint32_t* bb = &bh[nt >> 1][(nt & 1) * 2];
                        MMA_F16(acc[mt][nt], ah[mt][0], ah[mt][1], ah[mt][2], ah[mt][3], bb[0], bb[1]);
                    }
            }
        }
    } else {
        // ---------------- phi: 2-stage, 3 passes, 4 tiles ----------------
        CS = C2; n0 = ((int)blockIdx.x - 16) * 128; Ns = 256;
        const __half* tp[4] = { Ah + (size_t)m0 * KKc, Al + (size_t)m0 * KKc,
                                Bh2 + (size_t)n0 * KKc, Bl2 + (size_t)n0 * KKc };

        auto load_stage4 = [&](int c, int st) {
            const uint32_t base = sb + st * STG4;
            #pragma unroll
            for (int i = 0; i < 16; i++) {
                const int idx = tid + i * 128;       // 0..2047
                const int t   = idx >> 9;
                const int rem = idx & 511;
                const int row = rem >> 2;
                const int ch  = rem & 3;
                cp_async16(base + t * TILE + row * RB + ch * 16,
                           tp[t] + (size_t)row * KKc + c * 32 + ch * 8);
            }
            CP_COMMIT();
        };

        load_stage4(0, 0);

        for (int c = 0; c < NCH; c++) {
            if (c + 1 < NCH) { load_stage4(c + 1, (c + 1) & 1); CP_WAIT1(); }
            else             { CP_WAIT0(); }
            __syncthreads();

            const uint32_t stb = sb + (c & 1) * STG4;
            #pragma unroll
            for (int ks = 0; ks < 2; ks++) {
                const uint32_t ko = ks * 32;
                uint32_t ah[4][4], bh[4][4], xx[4][4];

                #pragma unroll
                for (int mt = 0; mt < 4; mt++)
                    LDSM4(ah[mt][0], ah[mt][1], ah[mt][2], ah[mt][3], stb + aOff[mt] + ko);
                #pragma unroll
                for (int nt2 = 0; nt2 < 4; nt2++)
                    LDSM4(bh[nt2][0], bh[nt2][1], bh[nt2][2], bh[nt2][3], stb + bOff[nt2] + ko);
                #pragma unroll
                for (int mt = 0; mt < 4; mt++)
                    #pragma unroll
                    for (int nt = 0; nt < 8; nt++) {
                        const uint32_t* bb = &bh[nt >> 1][(nt & 1) * 2];
                        MMA_F16(acc[mt][nt], ah[mt][0], ah[mt][1], ah[mt][2], ah[mt][3], bb[0], bb[1]);
                    }

                #pragma unroll
                for (int mt = 0; mt < 4; mt++)
                    LDSM4(xx[mt][0], xx[mt][1], xx[mt][2], xx[mt][3], stb + TILE + aOff[mt] + ko);
                #pragma unroll
                for (int mt = 0; mt < 4; mt++)
                    #pragma unroll
                    for (int nt = 0; nt < 8; nt++) {
                        const uint32_t* bb = &bh[nt >> 1][(nt & 1) * 2];
                        MMA_F16(acc[mt][nt], xx[mt][0], xx[mt][1], xx[mt][2], xx[mt][3], bb[0], bb[1]);
                    }

                #pragma unroll
                for (int nt2 = 0; nt2 < 4; nt2++)
                    LDSM4(xx[nt2][0], xx[nt2][1], xx[nt2][2], xx[nt2][3], stb + TILE + bOff[nt2] + ko);
                #pragma unroll
                for (int mt = 0; mt < 4; mt++)
                    #pragma unroll
                    for (int nt = 0; nt < 8; nt++) {
                        const uint32_t* bb = &xx[nt >> 1][(nt & 1) * 2];
                        MMA_F16(acc[mt][nt], ah[mt][0], ah[mt][1], ah[mt][2], ah[mt][3], bb[0], bb[1]);
                    }
            }
            __syncthreads();
        }
    }

    #pragma unroll
    for (int mt = 0; mt < 4; mt++) {
        const int m = m0 + wm + mt * 16 + (lane >> 2);
        #pragma unroll
        for (int nt = 0; nt < 8; nt++) {
            const int n = n0 + wn + nt * 8 + (lane & 3) * 2;
            *(float2*)(CS + (size_t)m * Ns + n)       = make_float2(acc[mt][nt][0], acc[mt][nt][1]);
            *(float2*)(CS + (size_t)(m + 8) * Ns + n) = make_float2(acc[mt][nt][2], acc[mt][nt][3]);
        }
    }
}

// ================= GEMM3: single-pass fp16 ==================
__global__ __launch_bounds__(128, 2)
void f16_gemm1(const __half* __restrict__ A, const __half* __restrict__ B,
               float* __restrict__ C)
{
    extern __shared__ char smem[];
    const uint32_t sb = smem_u32(smem);
    const int tid  = threadIdx.x;
    const int wid  = tid >> 5;
    const int lane = tid & 31;
    const int m0 = blockIdx.y * 128;
    const int n0 = blockIdx.x * 128;
    const int wm = (wid & 1) * 64;
    const int wn = (wid >> 1) * 64;

    const int g = lane >> 3, r = lane & 7;
    uint32_t aOff[4], bOff[4];
    #pragma unroll
    for (int mt = 0; mt < 4; mt++)
        aOff[mt] = (uint32_t)((wm + mt * 16 + (g & 1) * 8 + r) * RB + (g >> 1) * 16);
    #pragma unroll
    for (int nt2 = 0; nt2 < 4; nt2++)
        bOff[nt2] = (uint32_t)(TILE + (wn + nt2 * 16 + (g >> 1) * 8 + r) * RB + (g & 1) * 16);

    float acc[4][8][4];
    #pragma unroll
    for (int i = 0; i < 4; i++)
        #pragma unroll
        for (int j = 0; j < 8; j++)
            #pragma unroll
            for (int v = 0; v < 4; v++) acc[i][j][v] = 0.f;

    const __half* tp[2] = { A + (size_t)m0 * KKc, B + (size_t)n0 * KKc };

    auto load_stage = [&](int c, int st) {
        const uint32_t base = sb + st * STG2;
        #pragma unroll
        for (int t = 0; t < 2; t++) {
            const __half* src = tp[t] + c * 32;
            #pragma unroll
            for (int i = 0; i < 4; i++) {
                const int idx = tid + i * 128;
                const int row = idx >> 2;
                const int ch  = idx & 3;
                cp_async16(base + t * TILE + row * RB + ch * 16,
                           src + (size_t)row * KKc + ch * 8);
            }
        }
        CP_COMMIT();
    };

    load_stage(0, 0);
    load_stage(1, 1);

    for (int c = 0; c < NCH; c++) {
        if (c + 1 < NCH) CP_WAIT1(); else CP_WAIT0();
        __syncthreads();
        if (c + 2 < NCH) load_stage(c + 2, (c + 2) % 3);

        const uint32_t stb = sb + (c % 3) * STG2;
        #pragma unroll
        for (int ks = 0; ks < 2; ks++) {
            const uint32_t ko = ks * 32;
            uint32_t ah[4][4], bh[4][4];
            #pragma unroll
            for (int mt = 0; mt < 4; mt++)
                LDSM4(ah[mt][0], ah[mt][1], ah[mt][2], ah[mt][3], stb + aOff[mt] + ko);
            #pragma unroll
            for (int nt2 = 0; nt2 < 4; nt2++)
                LDSM4(bh[nt2][0], bh[nt2][1], bh[nt2][2], bh[nt2][3], stb + bOff[nt2] + ko);
            #pragma unroll
            for (int mt = 0; mt < 4; mt++)
                #pragma unroll
                for (int nt = 0; nt < 8; nt++) {
                    const uint32_t* bb = &bh[nt >> 1][(nt & 1) * 2];
                    MMA_F16(acc[mt][nt], ah[mt][0], ah[mt][1], ah[mt][2], ah[mt][3], bb[0], bb[1]);
                }
        }
    }

    #pragma unroll
    for (int mt = 0; mt < 4; mt++) {
        const int m = m0 + wm + mt * 16 + (lane >> 2);
        #pragma unroll
        for (int nt = 0; nt < 8; nt++) {
            const int n = n0 + wn + nt * 8 + (lane & 3) * 2;
            *(float2*)(C + (size_t)m * Dc + n)       = make_float2(acc[mt][nt][0], acc[mt][nt][1]);
            *(float2*)(C + (size_t)(m + 8) * Dc + n) = make_float2(acc[mt][nt][2], acc[mt][nt][3]);
        }
    }
}

// ---------------- fp32 -> fp16 hi/lo split ----------------
__global__ void split_f16(const float4* __restrict__ src,
                          uint2* __restrict__ H, uint2* __restrict__ L, int n4)
{
    int i = blockIdx.x * blockDim.x + threadIdx.x;
    if (i >= n4) return;
    float4 v = src[i];
    __half h0 = __float2half_rn(v.x), h1 = __float2half_rn(v.y);
    __half h2 = __float2half_rn(v.z), h3 = __float2half_rn(v.w);
    __half l0 = __float2half_rn(v.x - __half2float(h0));
    __half l1 = __float2half_rn(v.y - __half2float(h1));
    __half l2 = __float2half_rn(v.z - __half2float(h2));
    __half l3 = __float2half_rn(v.w - __half2float(h3));
    __half2 ha = {h0, h1}, hb = {h2, h3}, la = {l0, l1}, lb = {l2, l3};
    H[i] = make_uint2(*(uint32_t*)&ha, *(uint32_t*)&hb);
    L[i] = make_uint2(*(uint32_t*)&la, *(uint32_t*)&lb);
}

// ---------------- fp32 -> fp16 (single, rn) ----------------
__global__ void cvt_f16(const float4* __restrict__ src, uint2* __restrict__ H, int n4)
{
    int i = blockIdx.x * blockDim.x + threadIdx.x;
    if (i >= n4) return;
    float4 v = src[i];
    __half2 a = __floats2half2_rn(v.x, v.y);
    __half2 b = __floats2half2_rn(v.z, v.w);
    H[i] = make_uint2(*(uint32_t*)&a, *(uint32_t*)&b);
}

// ---------------- theta RMS scale (per-row rsqrt only) ----------------
__global__ void rms_scale(const float* __restrict__ X, float* __restrict__ scale, int cols)
{
    const int row = blockIdx.x;
    const float* xr = X + (size_t)row * cols;
    float ss = 0.f;
    for (int c = threadIdx.x * 4; c < cols; c += blockDim.x * 4) {
        float4 v = *(const float4*)(xr + c);
        ss += v.x * v.x + v.y * v.y + v.z * v.z + v.w * v.w;
    }
    #pragma unroll
    for (int o = 16; o > 0; o >>= 1) ss += __shfl_xor_sync(0xffffffffu, ss, o);
    __shared__ float red[32];
    const int warp = threadIdx.x >> 5, lane = threadIdx.x & 31;
    if (lane == 0) red[warp] = ss;
    __syncthreads();
    if (warp == 0) {
        ss = (lane < (blockDim.x >> 5)) ? red[lane] : 0.f;
        #pragma unroll
        for (int o = 16; o > 0; o >>= 1) ss += __shfl_xor_sync(0xffffffffu, ss, o);
        if (lane == 0) scale[row] = rsqrtf(ss / (float)cols + EPSV);
    }
}

// ---------------- fused RMSNorm(phi) + sincos transpose ----------------
__global__ __launch_bounds__(192)
void phi_rms_sincos(const float* __restrict__ phi, float2* __restrict__ sc)
{
    const int row = blockIdx.x;            // b*4096 + t
    const int t   = row & (Tc - 1);
    const int b   = row >> 12;
    const int j   = threadIdx.x;           // 0..191
    const float v = phi[(size_t)row * 256 + j];

    float ss = v * v;
    #pragma unroll
    for (int o = 16; o > 0; o >>= 1) ss += __shfl_xor_sync(0xffffffffu, ss, o);
    __shared__ float red[6];
    const int warp = j >> 5, lane = j & 31;
    if (lane == 0) red[warp] = ss;
    __syncthreads();
    float tot = red[0] + red[1] + red[2] + red[3] + red[4] + red[5];
    const float rs = rsqrtf(tot / (float)LHc + EPSV);

    float s, c;
    sincosf(v * rs, &s, &c);
    const int l = j >> 4, h = j & 15;
    sc[((size_t)(b * Hc + h) * Lc + l) * Tc + t] = make_float2(c * INVSQRT2, s * INVSQRT2);
}

// ---------------- fused 12-level butterfly -> fp16 ----------------
__global__ __launch_bounds__(512, 1)
void butterfly_fused(const float* __restrict__ theta, const float* __restrict__ tscale,
                     const float2* __restrict__ sc, __half* __restrict__ Th)
{
    extern __shared__ float th[];   // [4096][9]
    const int ds  = blockIdx.x;     // 0..15
    const int h   = blockIdx.y;     // 0..15
    const int b   = blockIdx.z;     // 0..1
    const int tid = threadIdx.x;
    const int cb  = h * 128 + ds * 8;
    const size_t rowbase = (size_t)b * Tc;

    #pragma unroll
    for (int k = 0; k < 8; k++) {
        const int t = tid + k * 512;
        const float scl = tscale[rowbase + t];
        const float* g = theta + (rowbase + t) * Dc + cb;
        float4 v0 = *(const float4*)g;
        float4 v1 = *(const float4*)(g + 4);
        float* s = &th[t * 9];
        s[0] = v0.x * scl; s[1] = v0.y * scl; s[2] = v0.z * scl; s[3] = v0.w * scl;
        s[4] = v1.x * scl; s[5] = v1.y * scl; s[6] = v1.z * scl; s[7] = v1.w * scl;
    }
    __syncthreads();

    const float2* scb = sc + (size_t)(b * Hc + h) * Lc * Tc;
    for (int l = 0; l < Lc; l++) {
        const int step = 1 << l;
        float2 w[8];
        #pragma unroll
        for (int k = 0; k < 8; k++) w[k] = scb[l * Tc + tid + k * 512];

        #pragma unroll
        for (int jh = 0; jh < 8; jh += 4) {
            float o[8][4];
            #pragma unroll
            for (int k = 0; k < 8; k++) {
                const int t = tid + k * 512;
                #pragma unroll
                for (int j = 0; j < 4; j++) {
                    float cur  = th[t * 9 + jh + j];
                    float prev = (t >= step) ? th[(t - step) * 9 + jh + j] : 0.f;
                    o[k][j] = fmaf(w[k].x, cur, w[k].y * prev);
                }
            }
            __syncthreads();
            #pragma unroll
            for (int k = 0; k < 8; k++) {
                const int t = tid + k * 512;
                #pragma unroll
                for (int j = 0; j < 4; j++) th[t * 9 + jh + j] = o[k][j];
            }
            __syncthreads();
        }
    }

    #pragma unroll
    for (int k = 0; k < 8; k++) {
        const int t = tid + k * 512;
        const float* s = &th[t * 9];
        __half hh[8];
        #pragma unroll
        for (int j = 0; j < 8; j++) hh[j] = __float2half_rn(s[j]);
        *(uint4*)(Th + (rowbase + t) * Dc + cb) = *(uint4*)hh;
    }
}

// ---------------- launcher ----------------
extern "C" void kernel_launch(void* const* d_in, const int* in_sizes, int n_in,
                              void* d_out, int out_size)
{
    const float* x     = (const float*)d_in[0];
    const float* W_tok = (const float*)d_in[1];
    const float* W_lvl = (const float*)d_in[2];
    const float* W_out = (const float*)d_in[3];
    float* out = (float*)d_out;

    __half *xh, *xl, *wth, *woh, *wlh, *wll, *thh;
    float *theta, *phi, *tscale; float2* sc;
    cudaGetSymbolAddress((void**)&xh,  g_xh);   cudaGetSymbolAddress((void**)&xl,  g_xl);
    cudaGetSymbolAddress((void**)&wth, g_wth);  cudaGetSymbolAddress((void**)&woh, g_woh);
    cudaGetSymbolAddress((void**)&wlh, g_wlh);  cudaGetSymbolAddress((void**)&wll, g_wll);
    cudaGetSymbolAddress((void**)&thh, g_thh);
    cudaGetSymbolAddress((void**)&theta,  g_theta);
    cudaGetSymbolAddress((void**)&phi,    g_phi);
    cudaGetSymbolAddress((void**)&tscale, g_tscale);
    cudaGetSymbolAddress((void**)&sc,     g_sc);

    const int SMEM_MAIN  = 2 * STG4;            // 81920 (covers 3*STG2=61440 too)
    const int SMEM_G3    = 3 * STG2;            // 61440
    const int SMEM_BFLY  = 4096 * 9 * 4;        // 147456
    cudaFuncSetAttribute(f16_gemm_main, cudaFuncAttributeMaxDynamicSharedMemorySize, SMEM_MAIN);
    cudaFuncSetAttribute(f16_gemm1, cudaFuncAttributeMaxDynamicSharedMemorySize, SMEM_G3);
    cudaFuncSetAttribute(butterfly_fused, cudaFuncAttributeMaxDynamicSharedMemorySize, SMEM_BFLY);

    // 1) operand conversions
    split_f16<<<(Mc * Dc / 4 + 255) / 256, 256>>>((const float4*)x, (uint2*)xh, (uint2*)xl, Mc * Dc / 4);
    cvt_f16<<<(Dc * Dc / 4 + 255) / 256, 256>>>((const float4*)W_tok, (uint2*)wth, Dc * Dc / 4);
    cvt_f16<<<(Dc * Dc / 4 + 255) / 256, 256>>>((const float4*)W_out, (uint2*)woh, Dc * Dc / 4);
    split_f16<<<(LHc * Dc / 4 + 255) / 256, 256>>>((const float4*)W_lvl, (uint2*)wlh, (uint2*)wll, LHc * Dc / 4);

    // 2) merged GEMM: theta (bx 0..15, 1-pass) + phi (bx 16..17, 3-pass)
    f16_gemm_main<<<dim3(18, Mc / 128), 128, SMEM_MAIN>>>(xh, xl, wth, theta, wlh, wll, phi);

    // 3) norms
    rms_scale<<<Mc, 256>>>(theta, tscale, Dc);
    phi_rms_sincos<<<Mc, 192>>>(phi, sc);

    // 4) fused butterfly (12 levels, applies tscale), emits fp16 theta
    butterfly_fused<<<dim3(16, Hc, 2), 512, SMEM_BFLY>>>(theta, tscale, sc, thh);

    // 5) y = theta @ W_out^T  (single-pass fp16)
    f16_gemm1<<<dim3(16, Mc / 128), 128, SMEM_G3>>>(thh, woh, out);
}

// round 12
// speedup vs baseline: 5.2727x; 1.0652x over previous
#include <cuda_runtime.h>
#include <cuda_fp16.h>
#include <cstdint>
#include <math.h>

// ---------------- problem shapes (fixed) ----------------
#define Tc   4096
#define Dc   2048
#define Hc   16
#define Lc   12
#define LHc  192
#define Mc   8192          // B*T
#define KKc  2048          // GEMM K
#define EPSV 1.1920929e-07f
#define INVSQRT2 0.70710678118654752440f

// ---------------- scratch (static device globals; zero-initialized) ----------
__device__ __half g_xh [(size_t)Mc * Dc];      // x fp16 hi
__device__ __half g_xl [(size_t)Mc * Dc];      // x fp16 lo (phi path only)
__device__ __half g_wth[(size_t)Dc * Dc];      // W_tok fp16
__device__ __half g_woh[(size_t)Dc * Dc];      // W_out fp16
__device__ __half g_wlh[(size_t)256 * Dc];     // W_lvl fp16 hi, padded 192->256 rows
__device__ __half g_wll[(size_t)256 * Dc];     // W_lvl fp16 lo
__device__ __half g_thh[(size_t)Mc * Dc];      // theta fp16 (single)
__device__ float g_theta [(size_t)Mc * Dc];
__device__ float g_phi   [(size_t)Mc * 256];   // padded cols
__device__ float g_tscale[(size_t)Mc];
__device__ float2 g_sc   [(size_t)2 * Hc * Lc * Tc];

// ---------------- PTX helpers ----------------
__device__ __forceinline__ uint32_t smem_u32(const void* p) {
    uint32_t a;
    asm("{ .reg .u64 t; cvta.to.shared.u64 t, %1; cvt.u32.u64 %0, t; }" : "=r"(a) : "l"(p));
    return a;
}
__device__ __forceinline__ void cp_async16(uint32_t s, const void* g) {
    asm volatile("cp.async.cg.shared.global [%0], [%1], 16;" :: "r"(s), "l"(g));
}
#define CP_COMMIT() asm volatile("cp.async.commit_group;" ::: "memory")
#define CP_WAIT1()  asm volatile("cp.async.wait_group 1;" ::: "memory")
#define CP_WAIT0()  asm volatile("cp.async.wait_group 0;" ::: "memory")

#define LDSM4(d0,d1,d2,d3,a) \
    asm volatile("ldmatrix.sync.aligned.m8n8.x4.shared.b16 {%0,%1,%2,%3}, [%4];" \
        : "=r"(d0), "=r"(d1), "=r"(d2), "=r"(d3) : "r"(a))

#define MMA_F16(c, a0,a1,a2,a3, b0,b1) \
    asm volatile("mma.sync.aligned.m16n8k16.row.col.f32.f16.f16.f32 " \
        "{%0,%1,%2,%3}, {%4,%5,%6,%7}, {%8,%9}, {%0,%1,%2,%3};" \
        : "+f"((c)[0]), "+f"((c)[1]), "+f"((c)[2]), "+f"((c)[3]) \
        : "r"(a0), "r"(a1), "r"(a2), "r"(a3), "r"(b0), "r"(b1))

#define RB    80                        // smem row bytes: 32 halves (64B) + 16B pad
#define TILE  (128 * RB)                // 10240 B per operand tile
#define STG2  (2 * TILE)                // 20480 (single-pass stage: A,B)
#define STG4  (4 * TILE)                // 40960 (phi stage: Ah,Al,Bh,Bl)
#define NCH   (KKc / 32)                // 64 chunks

// ============== merged GEMM: theta (1-pass) + phi (3-pass) ==================
// primary (bx<16):    C  = Ah @ B^T                 (3-stage, 2 tiles)
// secondary (bx>=16): C2 = AhBh2 + AlBh2 + AhBl2    (2-stage, 4 tiles)
// secondary warps whose columns are pure padding (>=LHc) skip MMA + epilogue.
__global__ __launch_bounds__(128, 2)
void f16_gemm_main(const __half* __restrict__ Ah, const __half* __restrict__ Al,
                   const __half* __restrict__ B, float* __restrict__ C,
                   const __half* __restrict__ Bh2, const __half* __restrict__ Bl2,
                   float* __restrict__ C2)
{
    extern __shared__ char smem[];
    const uint32_t sb = smem_u32(smem);
    const int tid  = threadIdx.x;
    const int wid  = tid >> 5;
    const int lane = tid & 31;
    const int m0 = blockIdx.y * 128;
    const int wm = (wid & 1) * 64;
    const int wn = (wid >> 1) * 64;
    const bool primary = (int)blockIdx.x < 16;

    const int g = lane >> 3, r = lane & 7;
    const int bTile = primary ? 1 : 2;      // B tile index within stage
    uint32_t aOff[4], bOff[4];
    #pragma unroll
    for (int mt = 0; mt < 4; mt++)
        aOff[mt] = (uint32_t)((wm + mt * 16 + (g & 1) * 8 + r) * RB + (g >> 1) * 16);
    #pragma unroll
    for (int nt2 = 0; nt2 < 4; nt2++)
        bOff[nt2] = (uint32_t)(bTile * TILE + (wn + nt2 * 16 + (g >> 1) * 8 + r) * RB + (g & 1) * 16);

    float acc[4][8][4];
    #pragma unroll
    for (int i = 0; i < 4; i++)
        #pragma unroll
        for (int j = 0; j < 8; j++)
            #pragma unroll
            for (int v = 0; v < 4; v++) acc[i][j][v] = 0.f;

    float* CS; int n0, Ns;
    bool active = true;

    if (primary) {
        // ---------------- theta: 3-stage, 1 pass, 2 tiles ----------------
        CS = C; n0 = blockIdx.x * 128; Ns = Dc;
        const __half* tp[2] = { Ah + (size_t)m0 * KKc, B + (size_t)n0 * KKc };

        auto load_stage = [&](int c, int st) {
            const uint32_t base = sb + st * STG2;
            #pragma unroll
            for (int t = 0; t < 2; t++) {
                const __half* src = tp[t] + c * 32;
                #pragma unroll
                for (int i = 0; i < 4; i++) {
                    const int idx = tid + i * 128;
                    const int row = idx >> 2;
                    const int ch  = idx & 3;
                    cp_async16(base + t * TILE + row * RB + ch * 16,
                               src + (size_t)row * KKc + ch * 8);
                }
            }
            CP_COMMIT();
        };

        load_stage(0, 0);
        load_stage(1, 1);

        for (int c = 0; c < NCH; c++) {
            if (c + 1 < NCH) CP_WAIT1(); else CP_WAIT0();
            __syncthreads();
            if (c + 2 < NCH) load_stage(c + 2, (c + 2) % 3);

            const uint32_t stb = sb + (c % 3) * STG2;
            #pragma unroll
            for (int ks = 0; ks < 2; ks++) {
                const uint32_t ko = ks * 32;
                uint32_t ah[4][4], bh[4][4];
                #pragma unroll
                for (int mt = 0; mt < 4; mt++)
                    LDSM4(ah[mt][0], ah[mt][1], ah[mt][2], ah[mt][3], stb + aOff[mt] + ko);
                #pragma unroll
                for (int nt2 = 0; nt2 < 4; nt2++)
                    LDSM4(bh[nt2][0], bh[nt2][1], bh[nt2][2], bh[nt2][3], stb + bOff[nt2] + ko);
                #pragma unroll
                for (int mt = 0; mt < 4; mt++)
                    #pragma unroll
                    for (int nt = 0; nt < 8; nt++) {
                        const uint32_t* bb = &bh[nt >> 1][(nt & 1) * 2];
                        MMA_F16(acc[mt][nt], ah[mt][0], ah[mt][1], ah[mt][2], ah[mt][3], bb[0], bb[1]);
                    }
            }
        }
    } else {
        // ---------------- phi: 2-stage, 3 passes, 4 tiles ----------------
        CS = C2; n0 = ((int)blockIdx.x - 16) * 128; Ns = 256;
        active = (n0 + wn) < LHc;              // skip pure-padding warp columns
        const __half* tp[4] = { Ah + (size_t)m0 * KKc, Al + (size_t)m0 * KKc,
                                Bh2 + (size_t)n0 * KKc, Bl2 + (size_t)n0 * KKc };

        auto load_stage4 = [&](int c, int st) {
            const uint32_t base = sb + st * STG4;
            #pragma unroll
            for (int i = 0; i < 16; i++) {
                const int idx = tid + i * 128;       // 0..2047
                const int t   = idx >> 9;
                const int rem = idx & 511;
                const int row = rem >> 2;
                const int ch  = rem & 3;
                cp_async16(base + t * TILE + row * RB + ch * 16,
                           tp[t] + (size_t)row * KKc + c * 32 + ch * 8);
            }
            CP_COMMIT();
        };

        load_stage4(0, 0);

        for (int c = 0; c < NCH; c++) {
            if (c + 1 < NCH) { load_stage4(c + 1, (c + 1) & 1); CP_WAIT1(); }
            else             { CP_WAIT0(); }
            __syncthreads();

            const uint32_t stb = sb + (c & 1) * STG4;
            if (active) {
                #pragma unroll
                for (int ks = 0; ks < 2; ks++) {
                    const uint32_t ko = ks * 32;
                    uint32_t ah[4][4], bh[4][4], xx[4][4];

                    #pragma unroll
                    for (int mt = 0; mt < 4; mt++)
                        LDSM4(ah[mt][0], ah[mt][1], ah[mt][2], ah[mt][3], stb + aOff[mt] + ko);
                    #pragma unroll
                    for (int nt2 = 0; nt2 < 4; nt2++)
                        LDSM4(bh[nt2][0], bh[nt2][1], bh[nt2][2], bh[nt2][3], stb + bOff[nt2] + ko);
                    #pragma unroll
                    for (int mt = 0; mt < 4; mt++)
                        #pragma unroll
                        for (int nt = 0; nt < 8; nt++) {
                            const uint32_t* bb = &bh[nt >> 1][(nt & 1) * 2];
                            MMA_F16(acc[mt][nt], ah[mt][0], ah[mt][1], ah[mt][2], ah[mt][3], bb[0], bb[1]);
                        }

                    #pragma unroll
                    for (int mt = 0; mt < 4; mt++)
                        LDSM4(xx[mt][0], xx[mt][1], xx[mt][2], xx[mt][3], stb + TILE + aOff[mt] + ko);
                    #pragma unroll
                    for (int mt = 0; mt < 4; mt++)
                        #pragma unroll
                        for (int nt = 0; nt < 8; nt++) {
                            const uint32_t* bb = &bh[nt >> 1][(nt & 1) * 2];
                            MMA_F16(acc[mt][nt], xx[mt][0], xx[mt][1], xx[mt][2], xx[mt][3], bb[0], bb[1]);
                        }

                    #pragma unroll
                    for (int nt2 = 0; nt2 < 4; nt2++)
                        LDSM4(xx[nt2][0], xx[nt2][1], xx[nt2][2], xx[nt2][3], stb + TILE + bOff[nt2] + ko);
                    #pragma unroll
                    for (int mt = 0; mt < 4; mt++)
                        #pragma unroll
                        for (int nt = 0; nt < 8; nt++) {
                            const uint32_t* bb = &xx[nt >> 1][(nt & 1) * 2];
                            MMA_F16(acc[mt][nt], ah[mt][0], ah[mt][1], ah[mt][2], ah[mt][3], bb[0], bb[1]);
                        }
                }
            }
            __syncthreads();
        }
    }

    if (active) {
        #pragma unroll
        for (int mt = 0; mt < 4; mt++) {
            const int m = m0 + wm + mt * 16 + (lane >> 2);
            #pragma unroll
            for (int nt = 0; nt < 8; nt++) {
                const int n = n0 + wn + nt * 8 + (lane & 3) * 2;
                *(float2*)(CS + (size_t)m * Ns + n)       = make_float2(acc[mt][nt][0], acc[mt][nt][1]);
                *(float2*)(CS + (size_t)(m + 8) * Ns + n) = make_float2(acc[mt][nt][2], acc[mt][nt][3]);
            }
        }
    }
}

// ================= GEMM3: single-pass fp16 ==================
__global__ __launch_bounds__(128, 2)
void f16_gemm1(const __half* __restrict__ A, const __half* __restrict__ B,
               float* __restrict__ C)
{
    extern __shared__ char smem[];
    const uint32_t sb = smem_u32(smem);
    const int tid  = threadIdx.x;
    const int wid  = tid >> 5;
    const int lane = tid & 31;
    const int m0 = blockIdx.y * 128;
    const int n0 = blockIdx.x * 128;
    const int wm = (wid & 1) * 64;
    const int wn = (wid >> 1) * 64;

    const int g = lane >> 3, r = lane & 7;
    uint32_t aOff[4], bOff[4];
    #pragma unroll
    for (int mt = 0; mt < 4; mt++)
        aOff[mt] = (uint32_t)((wm + mt * 16 + (g & 1) * 8 + r) * RB + (g >> 1) * 16);
    #pragma unroll
    for (int nt2 = 0; nt2 < 4; nt2++)
        bOff[nt2] = (uint32_t)(TILE + (wn + nt2 * 16 + (g >> 1) * 8 + r) * RB + (g & 1) * 16);

    float acc[4][8][4];
    #pragma unroll
    for (int i = 0; i < 4; i++)
        #pragma unroll
        for (int j = 0; j < 8; j++)
            #pragma unroll
            for (int v = 0; v < 4; v++) acc[i][j][v] = 0.f;

    const __half* tp[2] = { A + (size_t)m0 * KKc, B + (size_t)n0 * KKc };

    auto load_stage = [&](int c, int st) {
        const uint32_t base = sb + st * STG2;
        #pragma unroll
        for (int t = 0; t < 2; t++) {
            const __half* src = tp[t] + c * 32;
            #pragma unroll
            for (int i = 0; i < 4; i++) {
                const int idx = tid + i * 128;
                const int row = idx >> 2;
                const int ch  = idx & 3;
                cp_async16(base + t * TILE + row * RB + ch * 16,
                           src + (size_t)row * KKc + ch * 8);
            }
        }
        CP_COMMIT();
    };

    load_stage(0, 0);
    load_stage(1, 1);

    for (int c = 0; c < NCH; c++) {
        if (c + 1 < NCH) CP_WAIT1(); else CP_WAIT0();
        __syncthreads();
        if (c + 2 < NCH) load_stage(c + 2, (c + 2) % 3);

        const uint32_t stb = sb + (c % 3) * STG2;
        #pragma unroll
        for (int ks = 0; ks < 2; ks++) {
            const uint32_t ko = ks * 32;
            uint32_t ah[4][4], bh[4][4];
            #pragma unroll
            for (int mt = 0; mt < 4; mt++)
                LDSM4(ah[mt][0], ah[mt][1], ah[mt][2], ah[mt][3], stb + aOff[mt] + ko);
            #pragma unroll
            for (int nt2 = 0; nt2 < 4; nt2++)
                LDSM4(bh[nt2][0], bh[nt2][1], bh[nt2][2], bh[nt2][3], stb + bOff[nt2] + ko);
            #pragma unroll
            for (int mt = 0; mt < 4; mt++)
                #pragma unroll
                for (int nt = 0; nt < 8; nt++) {
                    const uint32_t* bb = &bh[nt >> 1][(nt & 1) * 2];
                    MMA_F16(acc[mt][nt], ah[mt][0], ah[mt][1], ah[mt][2], ah[mt][3], bb[0], bb[1]);
                }
        }
    }

    #pragma unroll
    for (int mt = 0; mt < 4; mt++) {
        const int m = m0 + wm + mt * 16 + (lane >> 2);
        #pragma unroll
        for (int nt = 0; nt < 8; nt++) {
            const int n = n0 + wn + nt * 8 + (lane & 3) * 2;
            *(float2*)(C + (size_t)m * Dc + n)       = make_float2(acc[mt][nt][0], acc[mt][nt][1]);
            *(float2*)(C + (size_t)(m + 8) * Dc + n) = make_float2(acc[mt][nt][2], acc[mt][nt][3]);
        }
    }
}

// ---------------- fp32 -> fp16 hi/lo split ----------------
__global__ void split_f16(const float4* __restrict__ src,
                          uint2* __restrict__ H, uint2* __restrict__ L, int n4)
{
    int i = blockIdx.x * blockDim.x + threadIdx.x;
    if (i >= n4) return;
    float4 v = src[i];
    __half h0 = __float2half_rn(v.x), h1 = __float2half_rn(v.y);
    __half h2 = __float2half_rn(v.z), h3 = __float2half_rn(v.w);
    __half l0 = __float2half_rn(v.x - __half2float(h0));
    __half l1 = __float2half_rn(v.y - __half2float(h1));
    __half l2 = __float2half_rn(v.z - __half2float(h2));
    __half l3 = __float2half_rn(v.w - __half2float(h3));
    __half2 ha = {h0, h1}, hb = {h2, h3}, la = {l0, l1}, lb = {l2, l3};
    H[i] = make_uint2(*(uint32_t*)&ha, *(uint32_t*)&hb);
    L[i] = make_uint2(*(uint32_t*)&la, *(uint32_t*)&lb);
}

// ---------------- fp32 -> fp16 (single, rn) ----------------
__global__ void cvt_f16(const float4* __restrict__ src, uint2* __restrict__ H, int n4)
{
    int i = blockIdx.x * blockDim.x + threadIdx.x;
    if (i >= n4) return;
    float4 v = src[i];
    __half2 a = __floats2half2_rn(v.x, v.y);
    __half2 b = __floats2half2_rn(v.z, v.w);
    H[i] = make_uint2(*(uint32_t*)&a, *(uint32_t*)&b);
}

// ---------------- theta RMS scale (per-row rsqrt only) ----------------
__global__ void rms_scale(const float* __restrict__ X, float* __restrict__ scale, int cols)
{
    const int row = blockIdx.x;
    const float* xr = X + (size_t)row * cols;
    float ss = 0.f;
    for (int c = threadIdx.x * 4; c < cols; c += blockDim.x * 4) {
        float4 v = *(const float4*)(xr + c);
        ss += v.x * v.x + v.y * v.y + v.z * v.z + v.w * v.w;
    }
    #pragma unroll
    for (int o = 16; o > 0; o >>= 1) ss += __shfl_xor_sync(0xffffffffu, ss, o);
    __shared__ float red[32];
    const int warp = threadIdx.x >> 5, lane = threadIdx.x & 31;
    if (lane == 0) red[warp] = ss;
    __syncthreads();
    if (warp == 0) {
        ss = (lane < (blockDim.x >> 5)) ? red[lane] : 0.f;
        #pragma unroll
        for (int o = 16; o > 0; o >>= 1) ss += __shfl_xor_sync(0xffffffffu, ss, o);
        if (lane == 0) scale[row] = rsqrtf(ss / (float)cols + EPSV);
    }
}

// ---------------- fused RMSNorm(phi) + sincos transpose ----------------
__global__ __launch_bounds__(192)
void phi_rms_sincos(const float* __restrict__ phi, float2* __restrict__ sc)
{
    const int row = blockIdx.x;            // b*4096 + t
    const int t   = row & (Tc - 1);
    const int b   = row >> 12;
    const int j   = threadIdx.x;           // 0..191
    const float v = phi[(size_t)row * 256 + j];

    float ss = v * v;
    #pragma unroll
    for (int o = 16; o > 0; o >>= 1) ss += __shfl_xor_sync(0xffffffffu, ss, o);
    __shared__ float red[6];
    const int warp = j >> 5, lane = j & 31;
    if (lane == 0) red[warp] = ss;
    __syncthreads();
    float tot = red[0] + red[1] + red[2] + red[3] + red[4] + red[5];
    const float rs = rsqrtf(tot / (float)LHc + EPSV);

    float s, c;
    sincosf(v * rs, &s, &c);
    const int l = j >> 4, h = j & 15;
    sc[((size_t)(b * Hc + h) * Lc + l) * Tc + t] = make_float2(c * INVSQRT2, s * INVSQRT2);
}

// ---------------- fused 12-level butterfly (register-resident) -> fp16 ------
// cur stays in registers; smem holds one copy for the shifted-neighbor read.
// Row stride 12 floats: 16B-aligned float4 access, conflict-free (banks 12l%32
// distinct within each 8-lane phase).
#define BSTR 12
__global__ __launch_bounds__(512, 1)
void butterfly_fused(const float* __restrict__ theta, const float* __restrict__ tscale,
                     const float2* __restrict__ sc, __half* __restrict__ Th)
{
    extern __shared__ float th[];   // [4096][BSTR]
    const int ds  = blockIdx.x;     // 0..15
    const int h   = blockIdx.y;     // 0..15
    const int b   = blockIdx.z;     // 0..1
    const int tid = threadIdx.x;
    const int cb  = h * 128 + ds * 8;
    const size_t rowbase = (size_t)b * Tc;

    float cur[8][8];

    #pragma unroll
    for (int k = 0; k < 8; k++) {
        const int t = tid + k * 512;
        const float scl = tscale[rowbase + t];
        const float* g = theta + (rowbase + t) * Dc + cb;
        float4 v0 = *(const float4*)g;
        float4 v1 = *(const float4*)(g + 4);
        cur[k][0] = v0.x * scl; cur[k][1] = v0.y * scl;
        cur[k][2] = v0.z * scl; cur[k][3] = v0.w * scl;
        cur[k][4] = v1.x * scl; cur[k][5] = v1.y * scl;
        cur[k][6] = v1.z * scl; cur[k][7] = v1.w * scl;
        float* s = &th[t * BSTR];
        *(float4*)s       = make_float4(cur[k][0], cur[k][1], cur[k][2], cur[k][3]);
        *(float4*)(s + 4) = make_float4(cur[k][4], cur[k][5], cur[k][6], cur[k][7]);
    }
    __syncthreads();

    const float2* scb = sc + (size_t)(b * Hc + h) * Lc * Tc;
    for (int l = 0; l < Lc; l++) {
        const int step = 1 << l;
        #pragma unroll
        for (int k = 0; k < 8; k++) {
            const int t = tid + k * 512;
            const float2 w = scb[l * Tc + t];
            float4 p0 = make_float4(0.f, 0.f, 0.f, 0.f);
            float4 p1 = p0;
            if (t >= step) {
                const float* ps = &th[(t - step) * BSTR];
                p0 = *(const float4*)ps;
                p1 = *(const float4*)(ps + 4);
            }
            cur[k][0] = fmaf(w.x, cur[k][0], w.y * p0.x);
            cur[k][1] = fmaf(w.x, cur[k][1], w.y * p0.y);
            cur[k][2] = fmaf(w.x, cur[k][2], w.y * p0.z);
            cur[k][3] = fmaf(w.x, cur[k][3], w.y * p0.w);
            cur[k][4] = fmaf(w.x, cur[k][4], w.y * p1.x);
            cur[k][5] = fmaf(w.x, cur[k][5], w.y * p1.y);
            cur[k][6] = fmaf(w.x, cur[k][6], w.y * p1.z);
            cur[k][7] = fmaf(w.x, cur[k][7], w.y * p1.w);
        }
        __syncthreads();                 // all reads of old level done
        if (l < Lc - 1) {
            #pragma unroll
            for (int k = 0; k < 8; k++) {
                float* s = &th[(tid + k * 512) * BSTR];
                *(float4*)s       = make_float4(cur[k][0], cur[k][1], cur[k][2], cur[k][3]);
                *(float4*)(s + 4) = make_float4(cur[k][4], cur[k][5], cur[k][6], cur[k][7]);
            }
            __syncthreads();             // new level visible
        }
    }

    #pragma unroll
    for (int k = 0; k < 8; k++) {
        const int t = tid + k * 512;
        __half hh[8];
        #pragma unroll
        for (int j = 0; j < 8; j++) hh[j] = __float2half_rn(cur[k][j]);
        *(uint4*)(Th + (rowbase + t) * Dc + cb) = *(uint4*)hh;
    }
}

// ---------------- launcher ----------------
extern "C" void kernel_launch(void* const* d_in, const int* in_sizes, int n_in,
                              void* d_out, int out_size)
{
    const float* x     = (const float*)d_in[0];
    const float* W_tok = (const float*)d_in[1];
    const float* W_lvl = (const float*)d_in[2];
    const float* W_out = (const float*)d_in[3];
    float* out = (float*)d_out;

    __half *xh, *xl, *wth, *woh, *wlh, *wll, *thh;
    float *theta, *phi, *tscale; float2* sc;
    cudaGetSymbolAddress((void**)&xh,  g_xh);   cudaGetSymbolAddress((void**)&xl,  g_xl);
    cudaGetSymbolAddress((void**)&wth, g_wth);  cudaGetSymbolAddress((void**)&woh, g_woh);
    cudaGetSymbolAddress((void**)&wlh, g_wlh);  cudaGetSymbolAddress((void**)&wll, g_wll);
    cudaGetSymbolAddress((void**)&thh, g_thh);
    cudaGetSymbolAddress((void**)&theta,  g_theta);
    cudaGetSymbolAddress((void**)&phi,    g_phi);
    cudaGetSymbolAddress((void**)&tscale, g_tscale);
    cudaGetSymbolAddress((void**)&sc,     g_sc);

    const int SMEM_MAIN  = 2 * STG4;            // 81920 (covers 3*STG2=61440 too)
    const int SMEM_G3    = 3 * STG2;            // 61440
    const int SMEM_BFLY  = 4096 * BSTR * 4;     // 196608
    cudaFuncSetAttribute(f16_gemm_main, cudaFuncAttributeMaxDynamicSharedMemorySize, SMEM_MAIN);
    cudaFuncSetAttribute(f16_gemm1, cudaFuncAttributeMaxDynamicSharedMemorySize, SMEM_G3);
    cudaFuncSetAttribute(butterfly_fused, cudaFuncAttributeMaxDynamicSharedMemorySize, SMEM_BFLY);

    // 1) operand conversions
    split_f16<<<(Mc * Dc / 4 + 255) / 256, 256>>>((const float4*)x, (uint2*)xh, (uint2*)xl, Mc * Dc / 4);
    cvt_f16<<<(Dc * Dc / 4 + 255) / 256, 256>>>((const float4*)W_tok, (uint2*)wth, Dc * Dc / 4);
    cvt_f16<<<(Dc * Dc / 4 + 255) / 256, 256>>>((const float4*)W_out, (uint2*)woh, Dc * Dc / 4);
    split_f16<<<(LHc * Dc / 4 + 255) / 256, 256>>>((const float4*)W_lvl, (uint2*)wlh, (uint2*)wll, LHc * Dc / 4);

    // 2) merged GEMM: theta (bx 0..15, 1-pass) + phi (bx 16..17, 3-pass trimmed)
    f16_gemm_main<<<dim3(18, Mc / 128), 128, SMEM_MAIN>>>(xh, xl, wth, theta, wlh, wll, phi);

    // 3) norms
    rms_scale<<<Mc, 256>>>(theta, tscale, Dc);
    phi_rms_sincos<<<Mc, 192>>>(phi, sc);

    // 4) fused butterfly (12 levels, applies tscale), emits fp16 theta
    butterfly_fused<<<dim3(16, Hc, 2), 512, SMEM_BFLY>>>(theta, tscale, sc, thh);

    // 5) y = theta @ W_out^T  (single-pass fp16)
    f16_gemm1<<<dim3(16, Mc / 128), 128, SMEM_G3>>>(thh, woh, out);
}

// round 13
// speedup vs baseline: 5.5114x; 1.0453x over previous
#include <cuda_runtime.h>
#include <cuda_fp16.h>
#include <cstdint>
#include <math.h>

// ---------------- problem shapes (fixed) ----------------
#define Tc   4096
#define Dc   2048
#define Hc   16
#define Lc   12
#define LHc  192
#define Mc   8192          // B*T
#define KKc  2048          // GEMM K
#define EPSV 1.1920929e-07f
#define INVSQRT2 0.70710678118654752440f

// ---------------- scratch (static device globals; zero-initialized) ----------
__device__ __half g_xh [(size_t)Mc * Dc];      // x fp16 hi
__device__ __half g_xl [(size_t)Mc * Dc];      // x fp16 lo (phi path only)
__device__ __half g_wth[(size_t)Dc * Dc];      // W_tok fp16
__device__ __half g_woh[(size_t)Dc * Dc];      // W_out fp16
__device__ __half g_wlh[(size_t)256 * Dc];     // W_lvl fp16 hi, padded 192->256 rows
__device__ __half g_wll[(size_t)256 * Dc];     // W_lvl fp16 lo
__device__ __half g_thh[(size_t)Mc * Dc];      // theta fp16 (pre-norm, then in-place butterfly)
__device__ float g_part  [(size_t)Mc * 32];    // per-(row, n-slab) sum-of-squares partials
__device__ float g_phi   [(size_t)Mc * 256];   // padded cols
__device__ float g_tscale[(size_t)Mc];
__device__ float2 g_sc   [(size_t)2 * Hc * Lc * Tc];

// ---------------- PTX helpers ----------------
__device__ __forceinline__ uint32_t smem_u32(const void* p) {
    uint32_t a;
    asm("{ .reg .u64 t; cvta.to.shared.u64 t, %1; cvt.u32.u64 %0, t; }" : "=r"(a) : "l"(p));
    return a;
}
__device__ __forceinline__ void cp_async16(uint32_t s, const void* g) {
    asm volatile("cp.async.cg.shared.global [%0], [%1], 16;" :: "r"(s), "l"(g));
}
#define CP_COMMIT() asm volatile("cp.async.commit_group;" ::: "memory")
#define CP_WAIT1()  asm volatile("cp.async.wait_group 1;" ::: "memory")
#define CP_WAIT0()  asm volatile("cp.async.wait_group 0;" ::: "memory")

#define LDSM4(d0,d1,d2,d3,a) \
    asm volatile("ldmatrix.sync.aligned.m8n8.x4.shared.b16 {%0,%1,%2,%3}, [%4];" \
        : "=r"(d0), "=r"(d1), "=r"(d2), "=r"(d3) : "r"(a))

#define MMA_F16(c, a0,a1,a2,a3, b0,b1) \
    asm volatile("mma.sync.aligned.m16n8k16.row.col.f32.f16.f16.f32 " \
        "{%0,%1,%2,%3}, {%4,%5,%6,%7}, {%8,%9}, {%0,%1,%2,%3};" \
        : "+f"((c)[0]), "+f"((c)[1]), "+f"((c)[2]), "+f"((c)[3]) \
        : "r"(a0), "r"(a1), "r"(a2), "r"(a3), "r"(b0), "r"(b1))

#define RB    80                        // smem row bytes: 32 halves (64B) + 16B pad
#define TILE  (128 * RB)                // 10240 B per operand tile
#define STG2  (2 * TILE)                // 20480 (single-pass stage: A,B)
#define STG4  (4 * TILE)                // 40960 (phi stage: Ah,Al,Bh,Bl)
#define NCH   (KKc / 32)                // 64 chunks

// ============== merged GEMM: theta (1-pass, fp16 out + ssq) + phi (3-pass) ===
// primary (bx<16):    Ct = fp16(Ah @ B^T); g_part[row][slot] = 64-col ssq
// secondary (bx>=16): C2 = AhBh2 + AlBh2 + AhBl2 (fp32), padding warps skip MMA
__global__ __launch_bounds__(128, 2)
void f16_gemm_main(const __half* __restrict__ Ah, const __half* __restrict__ Al,
                   const __half* __restrict__ B, __half* __restrict__ Ct,
                   float* __restrict__ part,
                   const __half* __restrict__ Bh2, const __half* __restrict__ Bl2,
                   float* __restrict__ C2)
{
    extern __shared__ char smem[];
    const uint32_t sb = smem_u32(smem);
    const int tid  = threadIdx.x;
    const int wid  = tid >> 5;
    const int lane = tid & 31;
    const int m0 = blockIdx.y * 128;
    const int wm = (wid & 1) * 64;
    const int wn = (wid >> 1) * 64;
    const bool primary = (int)blockIdx.x < 16;

    const int g = lane >> 3, r = lane & 7;
    const int bTile = primary ? 1 : 2;      // B tile index within stage
    uint32_t aOff[4], bOff[4];
    #pragma unroll
    for (int mt = 0; mt < 4; mt++)
        aOff[mt] = (uint32_t)((wm + mt * 16 + (g & 1) * 8 + r) * RB + (g >> 1) * 16);
    #pragma unroll
    for (int nt2 = 0; nt2 < 4; nt2++)
        bOff[nt2] = (uint32_t)(bTile * TILE + (wn + nt2 * 16 + (g >> 1) * 8 + r) * RB + (g & 1) * 16);

    float acc[4][8][4];
    #pragma unroll
    for (int i = 0; i < 4; i++)
        #pragma unroll
        for (int j = 0; j < 8; j++)
            #pragma unroll
            for (int v = 0; v < 4; v++) acc[i][j][v] = 0.f;

    if (primary) {
        // ---------------- theta: 3-stage, 1 pass, 2 tiles ----------------
        const int n0 = blockIdx.x * 128;
        const __half* tp[2] = { Ah + (size_t)m0 * KKc, B + (size_t)n0 * KKc };

        auto load_stage = [&](int c, int st) {
            const uint32_t base = sb + st * STG2;
            #pragma unroll
            for (int t = 0; t < 2; t++) {
                const __half* src = tp[t] + c * 32;
                #pragma unroll
                for (int i = 0; i < 4; i++) {
                    const int idx = tid + i * 128;
                    const int row = idx >> 2;
                    const int ch  = idx & 3;
                    cp_async16(base + t * TILE + row * RB + ch * 16,
                               src + (size_t)row * KKc + ch * 8);
                }
            }
            CP_COMMIT();
        };

        load_stage(0, 0);
        load_stage(1, 1);

        for (int c = 0; c < NCH; c++) {
            if (c + 1 < NCH) CP_WAIT1(); else CP_WAIT0();
            __syncthreads();
            if (c + 2 < NCH) load_stage(c + 2, (c + 2) % 3);

            const uint32_t stb = sb + (c % 3) * STG2;
            #pragma unroll
            for (int ks = 0; ks < 2; ks++) {
                const uint32_t ko = ks * 32;
                uint32_t ah[4][4], bh[4][4];
                #pragma unroll
                for (int mt = 0; mt < 4; mt++)
                    LDSM4(ah[mt][0], ah[mt][1], ah[mt][2], ah[mt][3], stb + aOff[mt] + ko);
                #pragma unroll
                for (int nt2 = 0; nt2 < 4; nt2++)
                    LDSM4(bh[nt2][0], bh[nt2][1], bh[nt2][2], bh[nt2][3], stb + bOff[nt2] + ko);
                #pragma unroll
                for (int mt = 0; mt < 4; mt++)
                    #pragma unroll
                    for (int nt = 0; nt < 8; nt++) {
                        const uint32_t* bb = &bh[nt >> 1][(nt & 1) * 2];
                        MMA_F16(acc[mt][nt], ah[mt][0], ah[mt][1], ah[mt][2], ah[mt][3], bb[0], bb[1]);
                    }
            }
        }

        // ---- epilogue: fp16 theta + deterministic ssq partials ----
        const int slot = blockIdx.x * 2 + (wn >> 6);
        #pragma unroll
        for (int mt = 0; mt < 4; mt++) {
            const int m = m0 + wm + mt * 16 + (lane >> 2);
            float ss0 = 0.f, ss1 = 0.f;
            #pragma unroll
            for (int nt = 0; nt < 8; nt++) {
                const int n = n0 + wn + nt * 8 + (lane & 3) * 2;
                const float a0 = acc[mt][nt][0], a1 = acc[mt][nt][1];
                const float a2 = acc[mt][nt][2], a3 = acc[mt][nt][3];
                *(__half2*)(Ct + (size_t)m * Dc + n)       = __floats2half2_rn(a0, a1);
                *(__half2*)(Ct + (size_t)(m + 8) * Dc + n) = __floats2half2_rn(a2, a3);
                ss0 = fmaf(a0, a0, fmaf(a1, a1, ss0));
                ss1 = fmaf(a2, a2, fmaf(a3, a3, ss1));
            }
            ss0 += __shfl_xor_sync(0xffffffffu, ss0, 1);
            ss0 += __shfl_xor_sync(0xffffffffu, ss0, 2);
            ss1 += __shfl_xor_sync(0xffffffffu, ss1, 1);
            ss1 += __shfl_xor_sync(0xffffffffu, ss1, 2);
            if ((lane & 3) == 0) {
                part[(size_t)m * 32 + slot]       = ss0;
                part[(size_t)(m + 8) * 32 + slot] = ss1;
            }
        }
    } else {
        // ---------------- phi: 2-stage, 3 passes, 4 tiles ----------------
        const int n0 = ((int)blockIdx.x - 16) * 128;
        const bool active = (n0 + wn) < LHc;       // skip pure-padding warp columns
        const __half* tp[4] = { Ah + (size_t)m0 * KKc, Al + (size_t)m0 * KKc,
                                Bh2 + (size_t)n0 * KKc, Bl2 + (size_t)n0 * KKc };

        auto load_stage4 = [&](int c, int st) {
            const uint32_t base = sb + st * STG4;
            #pragma unroll
            for (int i = 0; i < 16; i++) {
                const int idx = tid + i * 128;       // 0..2047
                const int t   = idx >> 9;
                const int rem = idx & 511;
                const int row = rem >> 2;
                const int ch  = rem & 3;
                cp_async16(base + t * TILE + row * RB + ch * 16,
                           tp[t] + (size_t)row * KKc + c * 32 + ch * 8);
            }
            CP_COMMIT();
        };

        load_stage4(0, 0);

        for (int c = 0; c < NCH; c++) {
            if (c + 1 < NCH) { load_stage4(c + 1, (c + 1) & 1); CP_WAIT1(); }
            else             { CP_WAIT0(); }
            __syncthreads();

            const uint32_t stb = sb + (c & 1) * STG4;
            if (active) {
                #pragma unroll
                for (int ks = 0; ks < 2; ks++) {
                    const uint32_t ko = ks * 32;
                    uint32_t ah[4][4], bh[4][4], xx[4][4];

                    #pragma unroll
                    for (int mt = 0; mt < 4; mt++)
                        LDSM4(ah[mt][0], ah[mt][1], ah[mt][2], ah[mt][3], stb + aOff[mt] + ko);
                    #pragma unroll
                    for (int nt2 = 0; nt2 < 4; nt2++)
                        LDSM4(bh[nt2][0], bh[nt2][1], bh[nt2][2], bh[nt2][3], stb + bOff[nt2] + ko);
                    #pragma unroll
                    for (int mt = 0; mt < 4; mt++)
                        #pragma unroll
                        for (int nt = 0; nt < 8; nt++) {
                            const uint32_t* bb = &bh[nt >> 1][(nt & 1) * 2];
                            MMA_F16(acc[mt][nt], ah[mt][0], ah[mt][1], ah[mt][2], ah[mt][3], bb[0], bb[1]);
                        }

                    #pragma unroll
                    for (int mt = 0; mt < 4; mt++)
                        LDSM4(xx[mt][0], xx[mt][1], xx[mt][2], xx[mt][3], stb + TILE + aOff[mt] + ko);
                    #pragma unroll
                    for (int mt = 0; mt < 4; mt++)
                        #pragma unroll
                        for (int nt = 0; nt < 8; nt++) {
                            const uint32_t* bb = &bh[nt >> 1][(nt & 1) * 2];
                            MMA_F16(acc[mt][nt], xx[mt][0], xx[mt][1], xx[mt][2], xx[mt][3], bb[0], bb[1]);
                        }

                    #pragma unroll
                    for (int nt2 = 0; nt2 < 4; nt2++)
                        LDSM4(xx[nt2][0], xx[nt2][1], xx[nt2][2], xx[nt2][3], stb + TILE + bOff[nt2] + ko);
                    #pragma unroll
                    for (int mt = 0; mt < 4; mt++)
                        #pragma unroll
                        for (int nt = 0; nt < 8; nt++) {
                            const uint32_t* bb = &xx[nt >> 1][(nt & 1) * 2];
                            MMA_F16(acc[mt][nt], ah[mt][0], ah[mt][1], ah[mt][2], ah[mt][3], bb[0], bb[1]);
                        }
                }
            }
            __syncthreads();
        }

        if (active) {
            #pragma unroll
            for (int mt = 0; mt < 4; mt++) {
                const int m = m0 + wm + mt * 16 + (lane >> 2);
                #pragma unroll
                for (int nt = 0; nt < 8; nt++) {
                    const int n = n0 + wn + nt * 8 + (lane & 3) * 2;
                    *(float2*)(C2 + (size_t)m * 256 + n)       = make_float2(acc[mt][nt][0], acc[mt][nt][1]);
                    *(float2*)(C2 + (size_t)(m + 8) * 256 + n) = make_float2(acc[mt][nt][2], acc[mt][nt][3]);
                }
            }
        }
    }
}

// ================= GEMM3: single-pass fp16 ==================
__global__ __launch_bounds__(128, 2)
void f16_gemm1(const __half* __restrict__ A, const __half* __restrict__ B,
               float* __restrict__ C)
{
    extern __shared__ char smem[];
    const uint32_t sb = smem_u32(smem);
    const int tid  = threadIdx.x;
    const int wid  = tid >> 5;
    const int lane = tid & 31;
    const int m0 = blockIdx.y * 128;
    const int n0 = blockIdx.x * 128;
    const int wm = (wid & 1) * 64;
    const int wn = (wid >> 1) * 64;

    const int g = lane >> 3, r = lane & 7;
    uint32_t aOff[4], bOff[4];
    #pragma unroll
    for (int mt = 0; mt < 4; mt++)
        aOff[mt] = (uint32_t)((wm + mt * 16 + (g & 1) * 8 + r) * RB + (g >> 1) * 16);
    #pragma unroll
    for (int nt2 = 0; nt2 < 4; nt2++)
        bOff[nt2] = (uint32_t)(TILE + (wn + nt2 * 16 + (g >> 1) * 8 + r) * RB + (g & 1) * 16);

    float acc[4][8][4];
    #pragma unroll
    for (int i = 0; i < 4; i++)
        #pragma unroll
        for (int j = 0; j < 8; j++)
            #pragma unroll
            for (int v = 0; v < 4; v++) acc[i][j][v] = 0.f;

    const __half* tp[2] = { A + (size_t)m0 * KKc, B + (size_t)n0 * KKc };

    auto load_stage = [&](int c, int st) {
        const uint32_t base = sb + st * STG2;
        #pragma unroll
        for (int t = 0; t < 2; t++) {
            const __half* src = tp[t] + c * 32;
            #pragma unroll
            for (int i = 0; i < 4; i++) {
                const int idx = tid + i * 128;
                const int row = idx >> 2;
                const int ch  = idx & 3;
                cp_async16(base + t * TILE + row * RB + ch * 16,
                           src + (size_t)row * KKc + ch * 8);
            }
        }
        CP_COMMIT();
    };

    load_stage(0, 0);
    load_stage(1, 1);

    for (int c = 0; c < NCH; c++) {
        if (c + 1 < NCH) CP_WAIT1(); else CP_WAIT0();
        __syncthreads();
        if (c + 2 < NCH) load_stage(c + 2, (c + 2) % 3);

        const uint32_t stb = sb + (c % 3) * STG2;
        #pragma unroll
        for (int ks = 0; ks < 2; ks++) {
            const uint32_t ko = ks * 32;
            uint32_t ah[4][4], bh[4][4];
            #pragma unroll
            for (int mt = 0; mt < 4; mt++)
                LDSM4(ah[mt][0], ah[mt][1], ah[mt][2], ah[mt][3], stb + aOff[mt] + ko);
            #pragma unroll
            for (int nt2 = 0; nt2 < 4; nt2++)
                LDSM4(bh[nt2][0], bh[nt2][1], bh[nt2][2], bh[nt2][3], stb + bOff[nt2] + ko);
            #pragma unroll
            for (int mt = 0; mt < 4; mt++)
                #pragma unroll
                for (int nt = 0; nt < 8; nt++) {
                    const uint32_t* bb = &bh[nt >> 1][(nt & 1) * 2];
                    MMA_F16(acc[mt][nt], ah[mt][0], ah[mt][1], ah[mt][2], ah[mt][3], bb[0], bb[1]);
                }
        }
    }

    #pragma unroll
    for (int mt = 0; mt < 4; mt++) {
        const int m = m0 + wm + mt * 16 + (lane >> 2);
        #pragma unroll
        for (int nt = 0; nt < 8; nt++) {
            const int n = n0 + wn + nt * 8 + (lane & 3) * 2;
            *(float2*)(C + (size_t)m * Dc + n)       = make_float2(acc[mt][nt][0], acc[mt][nt][1]);
            *(float2*)(C + (size_t)(m + 8) * Dc + n) = make_float2(acc[mt][nt][2], acc[mt][nt][3]);
        }
    }
}

// ---------------- fused operand conversions (one kernel) ----------------
__device__ __forceinline__ void split4(float4 v, uint2* H, uint2* L, int i) {
    __half h0 = __float2half_rn(v.x), h1 = __float2half_rn(v.y);
    __half h2 = __float2half_rn(v.z), h3 = __float2half_rn(v.w);
    __half l0 = __float2half_rn(v.x - __half2float(h0));
    __half l1 = __float2half_rn(v.y - __half2float(h1));
    __half l2 = __float2half_rn(v.z - __half2float(h2));
    __half l3 = __float2half_rn(v.w - __half2float(h3));
    __half2 ha = {h0, h1}, hb = {h2, h3}, la = {l0, l1}, lb = {l2, l3};
    H[i] = make_uint2(*(uint32_t*)&ha, *(uint32_t*)&hb);
    L[i] = make_uint2(*(uint32_t*)&la, *(uint32_t*)&lb);
}
__device__ __forceinline__ void cvt4(float4 v, uint2* H, int i) {
    __half2 a = __floats2half2_rn(v.x, v.y);
    __half2 b = __floats2half2_rn(v.z, v.w);
    H[i] = make_uint2(*(uint32_t*)&a, *(uint32_t*)&b);
}

#define N_X  (Mc * Dc / 4)
#define N_W  (Dc * Dc / 4)
#define N_L  (LHc * Dc / 4)
#define N_ALL (N_X + 2 * N_W + N_L)

__global__ void cvt_all(const float4* __restrict__ x, const float4* __restrict__ wt,
                        const float4* __restrict__ wo, const float4* __restrict__ wl,
                        uint2* __restrict__ xh, uint2* __restrict__ xl,
                        uint2* __restrict__ wth, uint2* __restrict__ woh,
                        uint2* __restrict__ wlh, uint2* __restrict__ wll)
{
    int i = blockIdx.x * blockDim.x + threadIdx.x;
    if (i < N_X) {
        split4(x[i], xh, xl, i);
    } else if (i < N_X + N_W) {
        int j = i - N_X;
        cvt4(wt[j], wth, j);
    } else if (i < N_X + 2 * N_W) {
        int j = i - N_X - N_W;
        cvt4(wo[j], woh, j);
    } else if (i < N_ALL) {
        int j = i - N_X - 2 * N_W;
        split4(wl[j], wlh, wll, j);
    }
}

// ------- fused: theta-scale finish + RMSNorm(phi) + sincos transpose -------
__global__ __launch_bounds__(192)
void phi_rms_sincos(const float* __restrict__ phi, const float* __restrict__ part,
                    float* __restrict__ tscale, float2* __restrict__ sc)
{
    const int row = blockIdx.x;            // b*4096 + t
    const int t   = row & (Tc - 1);
    const int b   = row >> 12;
    const int j   = threadIdx.x;           // 0..191

    // warp 0: finish theta rms scale from 32 slab partials
    if (j < 32) {
        float ss = part[(size_t)row * 32 + j];
        #pragma unroll
        for (int o = 16; o > 0; o >>= 1) ss += __shfl_xor_sync(0xffffffffu, ss, o);
        if (j == 0) tscale[row] = rsqrtf(ss / (float)Dc + EPSV);
    }

    const float v = phi[(size_t)row * 256 + j];
    float ss = v * v;
    #pragma unroll
    for (int o = 16; o > 0; o >>= 1) ss += __shfl_xor_sync(0xffffffffu, ss, o);
    __shared__ float red[6];
    const int warp = j >> 5, lane = j & 31;
    if (lane == 0) red[warp] = ss;
    __syncthreads();
    float tot = red[0] + red[1] + red[2] + red[3] + red[4] + red[5];
    const float rs = rsqrtf(tot / (float)LHc + EPSV);

    float s, c;
    sincosf(v * rs, &s, &c);
    const int l = j >> 4, h = j & 15;
    sc[((size_t)(b * Hc + h) * Lc + l) * Tc + t] = make_float2(c * INVSQRT2, s * INVSQRT2);
}

// ---------------- fused 12-level butterfly (fp16 in-place) ----------------
#define BSTR 12
__global__ __launch_bounds__(512, 1)
void butterfly_fused(__half* __restrict__ Th, const float* __restrict__ tscale,
                     const float2* __restrict__ sc)
{
    extern __shared__ float th[];   // [4096][BSTR]
    const int ds  = blockIdx.x;     // 0..15
    const int h   = blockIdx.y;     // 0..15
    const int b   = blockIdx.z;     // 0..1
    const int tid = threadIdx.x;
    const int cb  = h * 128 + ds * 8;
    const size_t rowbase = (size_t)b * Tc;

    float cur[8][8];

    #pragma unroll
    for (int k = 0; k < 8; k++) {
        const int t = tid + k * 512;
        const float scl = tscale[rowbase + t];
        uint4 raw = *(const uint4*)(Th + (rowbase + t) * Dc + cb);
        const __half2* hp = (const __half2*)&raw;
        #pragma unroll
        for (int p = 0; p < 4; p++) {
            float2 f = __half22float2(hp[p]);
            cur[k][p * 2]     = f.x * scl;
            cur[k][p * 2 + 1] = f.y * scl;
        }
        float* s = &th[t * BSTR];
        *(float4*)s       = make_float4(cur[k][0], cur[k][1], cur[k][2], cur[k][3]);
        *(float4*)(s + 4) = make_float4(cur[k][4], cur[k][5], cur[k][6], cur[k][7]);
    }
    __syncthreads();

    const float2* scb = sc + (size_t)(b * Hc + h) * Lc * Tc;
    for (int l = 0; l < Lc; l++) {
        const int step = 1 << l;
        #pragma unroll
        for (int k = 0; k < 8; k++) {
            const int t = tid + k * 512;
            const float2 w = scb[l * Tc + t];
            float4 p0 = make_float4(0.f, 0.f, 0.f, 0.f);
            float4 p1 = p0;
            if (t >= step) {
                const float* ps = &th[(t - step) * BSTR];
                p0 = *(const float4*)ps;
                p1 = *(const float4*)(ps + 4);
            }
            cur[k][0] = fmaf(w.x, cur[k][0], w.y * p0.x);
            cur[k][1] = fmaf(w.x, cur[k][1], w.y * p0.y);
            cur[k][2] = fmaf(w.x, cur[k][2], w.y * p0.z);
            cur[k][3] = fmaf(w.x, cur[k][3], w.y * p0.w);
            cur[k][4] = fmaf(w.x, cur[k][4], w.y * p1.x);
            cur[k][5] = fmaf(w.x, cur[k][5], w.y * p1.y);
            cur[k][6] = fmaf(w.x, cur[k][6], w.y * p1.z);
            cur[k][7] = fmaf(w.x, cur[k][7], w.y * p1.w);
        }
        __syncthreads();                 // all reads of old level done
        if (l < Lc - 1) {
            #pragma unroll
            for (int k = 0; k < 8; k++) {
                float* s = &th[(tid + k * 512) * BSTR];
                *(float4*)s       = make_float4(cur[k][0], cur[k][1], cur[k][2], cur[k][3]);
                *(float4*)(s + 4) = make_float4(cur[k][4], cur[k][5], cur[k][6], cur[k][7]);
            }
            __syncthreads();             // new level visible
        }
    }

    #pragma unroll
    for (int k = 0; k < 8; k++) {
        const int t = tid + k * 512;
        __half hh[8];
        #pragma unroll
        for (int j = 0; j < 8; j++) hh[j] = __float2half_rn(cur[k][j]);
        *(uint4*)(Th + (rowbase + t) * Dc + cb) = *(uint4*)hh;
    }
}

// ---------------- launcher ----------------
extern "C" void kernel_launch(void* const* d_in, const int* in_sizes, int n_in,
                              void* d_out, int out_size)
{
    const float* x     = (const float*)d_in[0];
    const float* W_tok = (const float*)d_in[1];
    const float* W_lvl = (const float*)d_in[2];
    const float* W_out = (const float*)d_in[3];
    float* out = (float*)d_out;

    __half *xh, *xl, *wth, *woh, *wlh, *wll, *thh;
    float *phi, *tscale, *part; float2* sc;
    cudaGetSymbolAddress((void**)&xh,  g_xh);   cudaGetSymbolAddress((void**)&xl,  g_xl);
    cudaGetSymbolAddress((void**)&wth, g_wth);  cudaGetSymbolAddress((void**)&woh, g_woh);
    cudaGetSymbolAddress((void**)&wlh, g_wlh);  cudaGetSymbolAddress((void**)&wll, g_wll);
    cudaGetSymbolAddress((void**)&thh, g_thh);
    cudaGetSymbolAddress((void**)&part,   g_part);
    cudaGetSymbolAddress((void**)&phi,    g_phi);
    cudaGetSymbolAddress((void**)&tscale, g_tscale);
    cudaGetSymbolAddress((void**)&sc,     g_sc);

    const int SMEM_MAIN  = 2 * STG4;            // 81920 (covers 3*STG2=61440 too)
    const int SMEM_G3    = 3 * STG2;            // 61440
    const int SMEM_BFLY  = 4096 * BSTR * 4;     // 196608
    cudaFuncSetAttribute(f16_gemm_main, cudaFuncAttributeMaxDynamicSharedMemorySize, SMEM_MAIN);
    cudaFuncSetAttribute(f16_gemm1, cudaFuncAttributeMaxDynamicSharedMemorySize, SMEM_G3);
    cudaFuncSetAttribute(butterfly_fused, cudaFuncAttributeMaxDynamicSharedMemorySize, SMEM_BFLY);

    // 1) all operand conversions in one kernel
    cvt_all<<<(N_ALL + 255) / 256, 256>>>((const float4*)x, (const float4*)W_tok,
                                          (const float4*)W_out, (const float4*)W_lvl,
                                          (uint2*)xh, (uint2*)xl, (uint2*)wth,
                                          (uint2*)woh, (uint2*)wlh, (uint2*)wll);

    // 2) merged GEMM: theta (fp16 out + ssq partials) + phi
    f16_gemm_main<<<dim3(18, Mc / 128), 128, SMEM_MAIN>>>(xh, xl, wth, thh, part,
                                                          wlh, wll, phi);

    // 3) fused theta-scale finish + RMSNorm(phi) + sincos
    phi_rms_sincos<<<Mc, 192>>>(phi, part, tscale, sc);

    // 4) fused butterfly (12 levels, applies tscale), fp16 in-place
    butterfly_fused<<<dim3(16, Hc, 2), 512, SMEM_BFLY>>>(thh, tscale, sc);

    // 5) y = theta @ W_out^T  (single-pass fp16)
    f16_gemm1<<<dim3(16, Mc / 128), 128, SMEM_G3>>>(thh, woh, out);
}